// round 1
// baseline (speedup 1.0000x reference)
#include <cuda_runtime.h>
#include <math.h>

// Problem constants
#define Bb 8
#define Cc 512
#define Tt 1024
#define BCT (Bb*Cc*Tt)      // 4,194,304
#define BTT (Bb*Tt*Tt)      // 8,388,608

// Scratch (static device globals: no allocation in kernel_launch)
__device__ float g_qre[BCT], g_qim[BCT];
__device__ float g_kre[BCT], g_kim[BCT];
__device__ float g_vre[BCT], g_vim[BCT];
__device__ float g_attn[BTT];
__device__ float g_ore[BCT], g_oim[BCT];

#define BK 16
#define BT 64
#define PAD 4

__device__ __forceinline__ float neg_inf() { return __int_as_float(0xff800000); }

// ---------------------------------------------------------------------------
// mixrot: dst_re[b,d,t] = cos(phi_d)*R - sin(phi_d)*I
//         dst_im[b,d,t] = sin(phi_d)*R + cos(phi_d)*I
// where R = sum_c W[d,c]*sre[b,c,t], I = sum_c W[d,c]*sim[b,c,t]
// GEMM M=C (d), N=T (t), K=C (c). Two outputs share the A (W) tile.
// grid: (T/64, C/64, B), block 256
// ---------------------------------------------------------------------------
__global__ __launch_bounds__(256) void mixrot_kernel(
    const float* __restrict__ W, const float* __restrict__ phi,
    const float* __restrict__ sre, const float* __restrict__ sim,
    float* __restrict__ dre, float* __restrict__ dim_)
{
    __shared__ float As[BK][BT + PAD];
    __shared__ float Bre[BK][BT];
    __shared__ float Bim[BK][BT];

    const int b  = blockIdx.z;
    const int m0 = blockIdx.y * BT;
    const int n0 = blockIdx.x * BT;

    const float* pre = sre + (size_t)b * Cc * Tt;
    const float* pim = sim + (size_t)b * Cc * Tt;

    const int tid = threadIdx.x;
    const int ty = tid >> 4;          // 0..15
    const int tx = tid & 15;          // 0..15

    // A loader: k = tid&15, rows m = (tid>>4)*4 .. +3
    const int a_k = tid & 15;
    const int a_m = (tid >> 4) * 4;
    // B loader: k = tid>>4, cols n = (tid&15)*4 (float4)
    const int b_k = tid >> 4;
    const int b_n = (tid & 15) * 4;

    float accR[4][4] = {};
    float accI[4][4] = {};

    for (int k0 = 0; k0 < Cc; k0 += BK) {
        #pragma unroll
        for (int i = 0; i < 4; i++)
            As[a_k][a_m + i] = W[(size_t)(m0 + a_m + i) * Cc + k0 + a_k];

        float4 br = *(const float4*)&pre[(size_t)(k0 + b_k) * Tt + n0 + b_n];
        float4 bi = *(const float4*)&pim[(size_t)(k0 + b_k) * Tt + n0 + b_n];
        *(float4*)&Bre[b_k][b_n] = br;
        *(float4*)&Bim[b_k][b_n] = bi;
        __syncthreads();

        #pragma unroll
        for (int kk = 0; kk < BK; kk++) {
            float4 a4  = *(const float4*)&As[kk][ty * 4];
            float4 br4 = *(const float4*)&Bre[kk][tx * 4];
            float4 bi4 = *(const float4*)&Bim[kk][tx * 4];
            float av[4]  = {a4.x,  a4.y,  a4.z,  a4.w};
            float brv[4] = {br4.x, br4.y, br4.z, br4.w};
            float biv[4] = {bi4.x, bi4.y, bi4.z, bi4.w};
            #pragma unroll
            for (int i = 0; i < 4; i++)
                #pragma unroll
                for (int j = 0; j < 4; j++) {
                    accR[i][j] += av[i] * brv[j];
                    accI[i][j] += av[i] * biv[j];
                }
        }
        __syncthreads();
    }

    float* qr = dre + (size_t)b * Cc * Tt;
    float* qi = dim_ + (size_t)b * Cc * Tt;
    #pragma unroll
    for (int i = 0; i < 4; i++) {
        const int m = m0 + ty * 4 + i;
        float sp, cp;
        sincosf(phi[m], &sp, &cp);
        float4 vr, vi;
        vr.x = accR[i][0]*cp - accI[i][0]*sp;  vi.x = accR[i][0]*sp + accI[i][0]*cp;
        vr.y = accR[i][1]*cp - accI[i][1]*sp;  vi.y = accR[i][1]*sp + accI[i][1]*cp;
        vr.z = accR[i][2]*cp - accI[i][2]*sp;  vi.z = accR[i][2]*sp + accI[i][2]*cp;
        vr.w = accR[i][3]*cp - accI[i][3]*sp;  vi.w = accR[i][3]*sp + accI[i][3]*cp;
        *(float4*)&qr[(size_t)m * Tt + n0 + tx * 4] = vr;
        *(float4*)&qi[(size_t)m * Tt + n0 + tx * 4] = vi;
    }
}

// ---------------------------------------------------------------------------
// scores: S[b,t,u] = (sum_c qre[c,t]*kre[c,u] + qim[c,t]*kim[c,u]) / 8
// causal: u > t -> -inf. Fully-masked tiles are skipped.
// grid: (T/64 (u), T/64 (t), B)
// ---------------------------------------------------------------------------
__global__ __launch_bounds__(256) void scores_kernel(
    const float* __restrict__ qre, const float* __restrict__ qim,
    const float* __restrict__ kre, const float* __restrict__ kim,
    float* __restrict__ attn)
{
    const int b  = blockIdx.z;
    const int t0 = blockIdx.y * BT;
    const int u0 = blockIdx.x * BT;
    const int tid = threadIdx.x;
    const int ty = tid >> 4, tx = tid & 15;

    float* arow = attn + (size_t)b * Tt * Tt;

    if (u0 > t0 + BT - 1) {
        // fully above the diagonal: -inf
        const float ni = neg_inf();
        float4 v = make_float4(ni, ni, ni, ni);
        #pragma unroll
        for (int i = 0; i < 4; i++)
            *(float4*)&arow[(size_t)(t0 + ty * 4 + i) * Tt + u0 + tx * 4] = v;
        return;
    }

    __shared__ float Aqr[BK][BT];
    __shared__ float Aqi[BK][BT];
    __shared__ float Bkr[BK][BT];
    __shared__ float Bki[BK][BT];

    const float* qr = qre + (size_t)b * Cc * Tt;
    const float* qi = qim + (size_t)b * Cc * Tt;
    const float* kr = kre + (size_t)b * Cc * Tt;
    const float* ki = kim + (size_t)b * Cc * Tt;

    const int l_k = tid >> 4;
    const int l_n = (tid & 15) * 4;

    float acc[4][4] = {};

    for (int k0 = 0; k0 < Cc; k0 += BK) {
        *(float4*)&Aqr[l_k][l_n] = *(const float4*)&qr[(size_t)(k0 + l_k) * Tt + t0 + l_n];
        *(float4*)&Aqi[l_k][l_n] = *(const float4*)&qi[(size_t)(k0 + l_k) * Tt + t0 + l_n];
        *(float4*)&Bkr[l_k][l_n] = *(const float4*)&kr[(size_t)(k0 + l_k) * Tt + u0 + l_n];
        *(float4*)&Bki[l_k][l_n] = *(const float4*)&ki[(size_t)(k0 + l_k) * Tt + u0 + l_n];
        __syncthreads();

        #pragma unroll
        for (int kk = 0; kk < BK; kk++) {
            float4 ar4 = *(const float4*)&Aqr[kk][ty * 4];
            float4 ai4 = *(const float4*)&Aqi[kk][ty * 4];
            float4 br4 = *(const float4*)&Bkr[kk][tx * 4];
            float4 bi4 = *(const float4*)&Bki[kk][tx * 4];
            float arv[4] = {ar4.x, ar4.y, ar4.z, ar4.w};
            float aiv[4] = {ai4.x, ai4.y, ai4.z, ai4.w};
            float brv[4] = {br4.x, br4.y, br4.z, br4.w};
            float biv[4] = {bi4.x, bi4.y, bi4.z, bi4.w};
            #pragma unroll
            for (int i = 0; i < 4; i++)
                #pragma unroll
                for (int j = 0; j < 4; j++) {
                    acc[i][j] += arv[i] * brv[j];
                    acc[i][j] += aiv[i] * biv[j];
                }
        }
        __syncthreads();
    }

    const float scale = 0.125f;  // 1/sqrt(64)
    const float ni = neg_inf();
    #pragma unroll
    for (int i = 0; i < 4; i++) {
        const int t = t0 + ty * 4 + i;
        float4 v;
        const int u = u0 + tx * 4;
        v.x = (u + 0 > t) ? ni : acc[i][0] * scale;
        v.y = (u + 1 > t) ? ni : acc[i][1] * scale;
        v.z = (u + 2 > t) ? ni : acc[i][2] * scale;
        v.w = (u + 3 > t) ? ni : acc[i][3] * scale;
        *(float4*)&arow[(size_t)t * Tt + u] = v;
    }
}

// ---------------------------------------------------------------------------
// softmax over u (1024) per row, in place. grid: (T, B), block 256
// ---------------------------------------------------------------------------
__global__ __launch_bounds__(256) void softmax_kernel(float* __restrict__ attn)
{
    const int t = blockIdx.x;
    const int b = blockIdx.y;
    float* row = attn + ((size_t)b * Tt + t) * Tt;
    const int tid = threadIdx.x;

    float4 v = ((const float4*)row)[tid];
    float m = fmaxf(fmaxf(v.x, v.y), fmaxf(v.z, v.w));

    __shared__ float red[8];
    #pragma unroll
    for (int o = 16; o > 0; o >>= 1)
        m = fmaxf(m, __shfl_xor_sync(0xffffffffu, m, o));
    if ((tid & 31) == 0) red[tid >> 5] = m;
    __syncthreads();
    if (tid == 0) {
        float mm = red[0];
        #pragma unroll
        for (int i = 1; i < 8; i++) mm = fmaxf(mm, red[i]);
        red[0] = mm;
    }
    __syncthreads();
    m = red[0];
    __syncthreads();

    float e0 = expf(v.x - m), e1 = expf(v.y - m);
    float e2 = expf(v.z - m), e3 = expf(v.w - m);
    float s = e0 + e1 + e2 + e3;
    #pragma unroll
    for (int o = 16; o > 0; o >>= 1)
        s += __shfl_xor_sync(0xffffffffu, s, o);
    if ((tid & 31) == 0) red[tid >> 5] = s;
    __syncthreads();
    if (tid == 0) {
        float ss = 0.f;
        #pragma unroll
        for (int i = 0; i < 8; i++) ss += red[i];
        red[0] = ss;
    }
    __syncthreads();
    const float inv = 1.0f / red[0];

    ((float4*)row)[tid] = make_float4(e0 * inv, e1 * inv, e2 * inv, e3 * inv);
}

// ---------------------------------------------------------------------------
// av: out_{re,im}[b,c,t] = sum_u v_{re,im}[b,c,u] * attn[b,t,u]
// K-loop bounded at t_tile_end (attn == 0 above diagonal).
// grid: (T/64 (t), C/64 (c), B)
// ---------------------------------------------------------------------------
__global__ __launch_bounds__(256) void av_kernel(
    const float* __restrict__ vre, const float* __restrict__ vim,
    const float* __restrict__ attn,
    float* __restrict__ ore, float* __restrict__ oim)
{
    __shared__ float Avr[BK][BT + PAD];
    __shared__ float Avi[BK][BT + PAD];
    __shared__ float Bs [BK][BT + PAD];

    const int b  = blockIdx.z;
    const int m0 = blockIdx.y * BT;   // c
    const int n0 = blockIdx.x * BT;   // t
    const int tid = threadIdx.x;
    const int ty = tid >> 4, tx = tid & 15;

    const float* vr = vre + (size_t)b * Cc * Tt;
    const float* vi = vim + (size_t)b * Cc * Tt;
    const float* ar = attn + (size_t)b * Tt * Tt;

    // transpose loaders: row r (0..63), k chunk kq (0,4,8,12)
    const int r  = tid >> 2;
    const int kq = (tid & 3) * 4;

    float accR[4][4] = {};
    float accI[4][4] = {};

    const int kend = n0 + BT;  // exclusive; attn zero beyond t

    for (int k0 = 0; k0 < kend; k0 += BK) {
        float4 a1 = *(const float4*)&vr[(size_t)(m0 + r) * Tt + k0 + kq];
        float4 a2 = *(const float4*)&vi[(size_t)(m0 + r) * Tt + k0 + kq];
        float4 b1 = *(const float4*)&ar[(size_t)(n0 + r) * Tt + k0 + kq];
        Avr[kq + 0][r] = a1.x; Avr[kq + 1][r] = a1.y; Avr[kq + 2][r] = a1.z; Avr[kq + 3][r] = a1.w;
        Avi[kq + 0][r] = a2.x; Avi[kq + 1][r] = a2.y; Avi[kq + 2][r] = a2.z; Avi[kq + 3][r] = a2.w;
        Bs [kq + 0][r] = b1.x; Bs [kq + 1][r] = b1.y; Bs [kq + 2][r] = b1.z; Bs [kq + 3][r] = b1.w;
        __syncthreads();

        #pragma unroll
        for (int kk = 0; kk < BK; kk++) {
            float4 ar4 = *(const float4*)&Avr[kk][ty * 4];
            float4 ai4 = *(const float4*)&Avi[kk][ty * 4];
            float4 b4  = *(const float4*)&Bs [kk][tx * 4];
            float arv[4] = {ar4.x, ar4.y, ar4.z, ar4.w};
            float aiv[4] = {ai4.x, ai4.y, ai4.z, ai4.w};
            float bv[4]  = {b4.x,  b4.y,  b4.z,  b4.w};
            #pragma unroll
            for (int i = 0; i < 4; i++)
                #pragma unroll
                for (int j = 0; j < 4; j++) {
                    accR[i][j] += arv[i] * bv[j];
                    accI[i][j] += aiv[i] * bv[j];
                }
        }
        __syncthreads();
    }

    float* pr = ore + (size_t)b * Cc * Tt;
    float* pi = oim + (size_t)b * Cc * Tt;
    #pragma unroll
    for (int i = 0; i < 4; i++) {
        const int m = m0 + ty * 4 + i;
        float4 vR = make_float4(accR[i][0], accR[i][1], accR[i][2], accR[i][3]);
        float4 vI = make_float4(accI[i][0], accI[i][1], accI[i][2], accI[i][3]);
        *(float4*)&pr[(size_t)m * Tt + n0 + tx * 4] = vR;
        *(float4*)&pi[(size_t)m * Tt + n0 + tx * 4] = vI;
    }
}

// ---------------------------------------------------------------------------
extern "C" void kernel_launch(void* const* d_in, const int* in_sizes, int n_in,
                              void* d_out, int out_size)
{
    const float* z_re  = (const float*)d_in[0];
    const float* z_im  = (const float*)d_in[1];
    const float* Wq    = (const float*)d_in[2];
    const float* phi_q = (const float*)d_in[3];
    const float* Wk    = (const float*)d_in[4];
    const float* phi_k = (const float*)d_in[5];
    const float* Wv    = (const float*)d_in[6];
    const float* phi_v = (const float*)d_in[7];
    const float* Wo    = (const float*)d_in[8];
    const float* phi_o = (const float*)d_in[9];

    float *qre, *qim, *kre, *kim, *vre, *vim, *attn, *ore, *oim;
    cudaGetSymbolAddress((void**)&qre,  g_qre);
    cudaGetSymbolAddress((void**)&qim,  g_qim);
    cudaGetSymbolAddress((void**)&kre,  g_kre);
    cudaGetSymbolAddress((void**)&kim,  g_kim);
    cudaGetSymbolAddress((void**)&vre,  g_vre);
    cudaGetSymbolAddress((void**)&vim,  g_vim);
    cudaGetSymbolAddress((void**)&attn, g_attn);
    cudaGetSymbolAddress((void**)&ore,  g_ore);
    cudaGetSymbolAddress((void**)&oim,  g_oim);

    float* out_re = (float*)d_out;
    float* out_im = out_re + (size_t)BCT;

    dim3 blk(256);
    dim3 gproj(Tt / BT, Cc / BT, Bb);   // (16, 8, 8)
    dim3 gsc(Tt / BT, Tt / BT, Bb);     // (16, 16, 8)
    dim3 gsm(Tt, Bb);

    mixrot_kernel<<<gproj, blk>>>(Wq, phi_q, z_re, z_im, qre, qim);
    mixrot_kernel<<<gproj, blk>>>(Wk, phi_k, z_re, z_im, kre, kim);
    mixrot_kernel<<<gproj, blk>>>(Wv, phi_v, z_re, z_im, vre, vim);
    scores_kernel<<<gsc, blk>>>(qre, qim, kre, kim, attn);
    softmax_kernel<<<gsm, blk>>>(attn);
    av_kernel<<<gproj, blk>>>(vre, vim, attn, ore, oim);
    mixrot_kernel<<<gproj, blk>>>(Wo, phi_o, ore, oim, out_re, out_im);
}

// round 2
// speedup vs baseline: 1.0608x; 1.0608x over previous
#include <cuda_runtime.h>
#include <math.h>

// Problem constants
#define Bb 8
#define Cc 512
#define Tt 1024
#define BCT (Bb*Cc*Tt)      // 4,194,304
#define BTT (Bb*Tt*Tt)      // 8,388,608

// Scratch (static device globals: no allocation in kernel_launch)
__device__ float g_qre[BCT], g_qim[BCT];
__device__ float g_kre[BCT], g_kim[BCT];
__device__ float g_vre[BCT], g_vim[BCT];
__device__ float g_attn[BTT];
__device__ float g_ore[BCT], g_oim[BCT];

#define BK 16
#define BT 64
#define PAD 4

__device__ __forceinline__ float neg_inf() { return __int_as_float(0xff800000); }

// ---------------------------------------------------------------------------
// mixrot: dst_re[b,d,t] = cos(phi_d)*R - sin(phi_d)*I
//         dst_im[b,d,t] = sin(phi_d)*R + cos(phi_d)*I
// where R = sum_c W[d,c]*sre[b,c,t], I = sum_c W[d,c]*sim[b,c,t]
// GEMM M=C (d), N=T (t), K=C (c). Two outputs share the A (W) tile.
// grid: (T/64, C/64, B), block 256
// ---------------------------------------------------------------------------
__global__ __launch_bounds__(256) void mixrot_kernel(
    const float* __restrict__ W, const float* __restrict__ phi,
    const float* __restrict__ sre, const float* __restrict__ sim,
    float* __restrict__ dre, float* __restrict__ dim_)
{
    __shared__ float As[BK][BT + PAD];
    __shared__ float Bre[BK][BT];
    __shared__ float Bim[BK][BT];

    const int b  = blockIdx.z;
    const int m0 = blockIdx.y * BT;
    const int n0 = blockIdx.x * BT;

    const float* pre = sre + (size_t)b * Cc * Tt;
    const float* pim = sim + (size_t)b * Cc * Tt;

    const int tid = threadIdx.x;
    const int ty = tid >> 4;          // 0..15
    const int tx = tid & 15;          // 0..15

    // A loader: k = tid&15, rows m = (tid>>4)*4 .. +3
    const int a_k = tid & 15;
    const int a_m = (tid >> 4) * 4;
    // B loader: k = tid>>4, cols n = (tid&15)*4 (float4)
    const int b_k = tid >> 4;
    const int b_n = (tid & 15) * 4;

    float accR[4][4] = {};
    float accI[4][4] = {};

    for (int k0 = 0; k0 < Cc; k0 += BK) {
        #pragma unroll
        for (int i = 0; i < 4; i++)
            As[a_k][a_m + i] = W[(size_t)(m0 + a_m + i) * Cc + k0 + a_k];

        float4 br = *(const float4*)&pre[(size_t)(k0 + b_k) * Tt + n0 + b_n];
        float4 bi = *(const float4*)&pim[(size_t)(k0 + b_k) * Tt + n0 + b_n];
        *(float4*)&Bre[b_k][b_n] = br;
        *(float4*)&Bim[b_k][b_n] = bi;
        __syncthreads();

        #pragma unroll
        for (int kk = 0; kk < BK; kk++) {
            float4 a4  = *(const float4*)&As[kk][ty * 4];
            float4 br4 = *(const float4*)&Bre[kk][tx * 4];
            float4 bi4 = *(const float4*)&Bim[kk][tx * 4];
            float av[4]  = {a4.x,  a4.y,  a4.z,  a4.w};
            float brv[4] = {br4.x, br4.y, br4.z, br4.w};
            float biv[4] = {bi4.x, bi4.y, bi4.z, bi4.w};
            #pragma unroll
            for (int i = 0; i < 4; i++)
                #pragma unroll
                for (int j = 0; j < 4; j++) {
                    accR[i][j] += av[i] * brv[j];
                    accI[i][j] += av[i] * biv[j];
                }
        }
        __syncthreads();
    }

    float* qr = dre + (size_t)b * Cc * Tt;
    float* qi = dim_ + (size_t)b * Cc * Tt;
    #pragma unroll
    for (int i = 0; i < 4; i++) {
        const int m = m0 + ty * 4 + i;
        float sp, cp;
        sincosf(phi[m], &sp, &cp);
        float4 vr, vi;
        vr.x = accR[i][0]*cp - accI[i][0]*sp;  vi.x = accR[i][0]*sp + accI[i][0]*cp;
        vr.y = accR[i][1]*cp - accI[i][1]*sp;  vi.y = accR[i][1]*sp + accI[i][1]*cp;
        vr.z = accR[i][2]*cp - accI[i][2]*sp;  vi.z = accR[i][2]*sp + accI[i][2]*cp;
        vr.w = accR[i][3]*cp - accI[i][3]*sp;  vi.w = accR[i][3]*sp + accI[i][3]*cp;
        *(float4*)&qr[(size_t)m * Tt + n0 + tx * 4] = vr;
        *(float4*)&qi[(size_t)m * Tt + n0 + tx * 4] = vi;
    }
}

// ---------------------------------------------------------------------------
// scores: S[b,t,u] = (sum_c qre[c,t]*kre[c,u] + qim[c,t]*kim[c,u]) / 8
// causal: u > t -> -inf. Fully-masked tiles are skipped.
// grid: (T/64 (u), T/64 (t), B)
// ---------------------------------------------------------------------------
__global__ __launch_bounds__(256) void scores_kernel(
    const float* __restrict__ qre, const float* __restrict__ qim,
    const float* __restrict__ kre, const float* __restrict__ kim,
    float* __restrict__ attn)
{
    const int b  = blockIdx.z;
    const int t0 = blockIdx.y * BT;
    const int u0 = blockIdx.x * BT;
    const int tid = threadIdx.x;
    const int ty = tid >> 4, tx = tid & 15;

    float* arow = attn + (size_t)b * Tt * Tt;

    if (u0 > t0 + BT - 1) {
        // fully above the diagonal: -inf
        const float ni = neg_inf();
        float4 v = make_float4(ni, ni, ni, ni);
        #pragma unroll
        for (int i = 0; i < 4; i++)
            *(float4*)&arow[(size_t)(t0 + ty * 4 + i) * Tt + u0 + tx * 4] = v;
        return;
    }

    __shared__ float Aqr[BK][BT];
    __shared__ float Aqi[BK][BT];
    __shared__ float Bkr[BK][BT];
    __shared__ float Bki[BK][BT];

    const float* qr = qre + (size_t)b * Cc * Tt;
    const float* qi = qim + (size_t)b * Cc * Tt;
    const float* kr = kre + (size_t)b * Cc * Tt;
    const float* ki = kim + (size_t)b * Cc * Tt;

    const int l_k = tid >> 4;
    const int l_n = (tid & 15) * 4;

    float acc[4][4] = {};

    for (int k0 = 0; k0 < Cc; k0 += BK) {
        *(float4*)&Aqr[l_k][l_n] = *(const float4*)&qr[(size_t)(k0 + l_k) * Tt + t0 + l_n];
        *(float4*)&Aqi[l_k][l_n] = *(const float4*)&qi[(size_t)(k0 + l_k) * Tt + t0 + l_n];
        *(float4*)&Bkr[l_k][l_n] = *(const float4*)&kr[(size_t)(k0 + l_k) * Tt + u0 + l_n];
        *(float4*)&Bki[l_k][l_n] = *(const float4*)&ki[(size_t)(k0 + l_k) * Tt + u0 + l_n];
        __syncthreads();

        #pragma unroll
        for (int kk = 0; kk < BK; kk++) {
            float4 ar4 = *(const float4*)&Aqr[kk][ty * 4];
            float4 ai4 = *(const float4*)&Aqi[kk][ty * 4];
            float4 br4 = *(const float4*)&Bkr[kk][tx * 4];
            float4 bi4 = *(const float4*)&Bki[kk][tx * 4];
            float arv[4] = {ar4.x, ar4.y, ar4.z, ar4.w};
            float aiv[4] = {ai4.x, ai4.y, ai4.z, ai4.w};
            float brv[4] = {br4.x, br4.y, br4.z, br4.w};
            float biv[4] = {bi4.x, bi4.y, bi4.z, bi4.w};
            #pragma unroll
            for (int i = 0; i < 4; i++)
                #pragma unroll
                for (int j = 0; j < 4; j++) {
                    acc[i][j] += arv[i] * brv[j];
                    acc[i][j] += aiv[i] * biv[j];
                }
        }
        __syncthreads();
    }

    const float scale = 0.125f;  // 1/sqrt(64)
    const float ni = neg_inf();
    #pragma unroll
    for (int i = 0; i < 4; i++) {
        const int t = t0 + ty * 4 + i;
        float4 v;
        const int u = u0 + tx * 4;
        v.x = (u + 0 > t) ? ni : acc[i][0] * scale;
        v.y = (u + 1 > t) ? ni : acc[i][1] * scale;
        v.z = (u + 2 > t) ? ni : acc[i][2] * scale;
        v.w = (u + 3 > t) ? ni : acc[i][3] * scale;
        *(float4*)&arow[(size_t)t * Tt + u] = v;
    }
}

// ---------------------------------------------------------------------------
// softmax over u (1024) per row, in place. grid: (T, B), block 256
// ---------------------------------------------------------------------------
__global__ __launch_bounds__(256) void softmax_kernel(float* __restrict__ attn)
{
    const int t = blockIdx.x;
    const int b = blockIdx.y;
    float* row = attn + ((size_t)b * Tt + t) * Tt;
    const int tid = threadIdx.x;

    float4 v = ((const float4*)row)[tid];
    float m = fmaxf(fmaxf(v.x, v.y), fmaxf(v.z, v.w));

    __shared__ float red[8];
    #pragma unroll
    for (int o = 16; o > 0; o >>= 1)
        m = fmaxf(m, __shfl_xor_sync(0xffffffffu, m, o));
    if ((tid & 31) == 0) red[tid >> 5] = m;
    __syncthreads();
    if (tid == 0) {
        float mm = red[0];
        #pragma unroll
        for (int i = 1; i < 8; i++) mm = fmaxf(mm, red[i]);
        red[0] = mm;
    }
    __syncthreads();
    m = red[0];
    __syncthreads();

    float e0 = expf(v.x - m), e1 = expf(v.y - m);
    float e2 = expf(v.z - m), e3 = expf(v.w - m);
    float s = e0 + e1 + e2 + e3;
    #pragma unroll
    for (int o = 16; o > 0; o >>= 1)
        s += __shfl_xor_sync(0xffffffffu, s, o);
    if ((tid & 31) == 0) red[tid >> 5] = s;
    __syncthreads();
    if (tid == 0) {
        float ss = 0.f;
        #pragma unroll
        for (int i = 0; i < 8; i++) ss += red[i];
        red[0] = ss;
    }
    __syncthreads();
    const float inv = 1.0f / red[0];

    ((float4*)row)[tid] = make_float4(e0 * inv, e1 * inv, e2 * inv, e3 * inv);
}

// ---------------------------------------------------------------------------
// av: out_{re,im}[b,c,t] = sum_u v_{re,im}[b,c,u] * attn[b,t,u]
// K-loop bounded at t_tile_end (attn == 0 above diagonal).
// grid: (T/64 (t), C/64 (c), B)
// ---------------------------------------------------------------------------
__global__ __launch_bounds__(256) void av_kernel(
    const float* __restrict__ vre, const float* __restrict__ vim,
    const float* __restrict__ attn,
    float* __restrict__ ore, float* __restrict__ oim)
{
    __shared__ float Avr[BK][BT + PAD];
    __shared__ float Avi[BK][BT + PAD];
    __shared__ float Bs [BK][BT + PAD];

    const int b  = blockIdx.z;
    const int m0 = blockIdx.y * BT;   // c
    const int n0 = blockIdx.x * BT;   // t
    const int tid = threadIdx.x;
    const int ty = tid >> 4, tx = tid & 15;

    const float* vr = vre + (size_t)b * Cc * Tt;
    const float* vi = vim + (size_t)b * Cc * Tt;
    const float* ar = attn + (size_t)b * Tt * Tt;

    // transpose loaders: row r (0..63), k chunk kq (0,4,8,12)
    const int r  = tid >> 2;
    const int kq = (tid & 3) * 4;

    float accR[4][4] = {};
    float accI[4][4] = {};

    const int kend = n0 + BT;  // exclusive; attn zero beyond t

    for (int k0 = 0; k0 < kend; k0 += BK) {
        float4 a1 = *(const float4*)&vr[(size_t)(m0 + r) * Tt + k0 + kq];
        float4 a2 = *(const float4*)&vi[(size_t)(m0 + r) * Tt + k0 + kq];
        float4 b1 = *(const float4*)&ar[(size_t)(n0 + r) * Tt + k0 + kq];
        Avr[kq + 0][r] = a1.x; Avr[kq + 1][r] = a1.y; Avr[kq + 2][r] = a1.z; Avr[kq + 3][r] = a1.w;
        Avi[kq + 0][r] = a2.x; Avi[kq + 1][r] = a2.y; Avi[kq + 2][r] = a2.z; Avi[kq + 3][r] = a2.w;
        Bs [kq + 0][r] = b1.x; Bs [kq + 1][r] = b1.y; Bs [kq + 2][r] = b1.z; Bs [kq + 3][r] = b1.w;
        __syncthreads();

        #pragma unroll
        for (int kk = 0; kk < BK; kk++) {
            float4 ar4 = *(const float4*)&Avr[kk][ty * 4];
            float4 ai4 = *(const float4*)&Avi[kk][ty * 4];
            float4 b4  = *(const float4*)&Bs [kk][tx * 4];
            float arv[4] = {ar4.x, ar4.y, ar4.z, ar4.w};
            float aiv[4] = {ai4.x, ai4.y, ai4.z, ai4.w};
            float bv[4]  = {b4.x,  b4.y,  b4.z,  b4.w};
            #pragma unroll
            for (int i = 0; i < 4; i++)
                #pragma unroll
                for (int j = 0; j < 4; j++) {
                    accR[i][j] += arv[i] * bv[j];
                    accI[i][j] += aiv[i] * bv[j];
                }
        }
        __syncthreads();
    }

    float* pr = ore + (size_t)b * Cc * Tt;
    float* pi = oim + (size_t)b * Cc * Tt;
    #pragma unroll
    for (int i = 0; i < 4; i++) {
        const int m = m0 + ty * 4 + i;
        float4 vR = make_float4(accR[i][0], accR[i][1], accR[i][2], accR[i][3]);
        float4 vI = make_float4(accI[i][0], accI[i][1], accI[i][2], accI[i][3]);
        *(float4*)&pr[(size_t)m * Tt + n0 + tx * 4] = vR;
        *(float4*)&pi[(size_t)m * Tt + n0 + tx * 4] = vI;
    }
}

// ---------------------------------------------------------------------------
extern "C" void kernel_launch(void* const* d_in, const int* in_sizes, int n_in,
                              void* d_out, int out_size)
{
    const float* z_re  = (const float*)d_in[0];
    const float* z_im  = (const float*)d_in[1];
    const float* Wq    = (const float*)d_in[2];
    const float* phi_q = (const float*)d_in[3];
    const float* Wk    = (const float*)d_in[4];
    const float* phi_k = (const float*)d_in[5];
    const float* Wv    = (const float*)d_in[6];
    const float* phi_v = (const float*)d_in[7];
    const float* Wo    = (const float*)d_in[8];
    const float* phi_o = (const float*)d_in[9];

    float *qre, *qim, *kre, *kim, *vre, *vim, *attn, *ore, *oim;
    cudaGetSymbolAddress((void**)&qre,  g_qre);
    cudaGetSymbolAddress((void**)&qim,  g_qim);
    cudaGetSymbolAddress((void**)&kre,  g_kre);
    cudaGetSymbolAddress((void**)&kim,  g_kim);
    cudaGetSymbolAddress((void**)&vre,  g_vre);
    cudaGetSymbolAddress((void**)&vim,  g_vim);
    cudaGetSymbolAddress((void**)&attn, g_attn);
    cudaGetSymbolAddress((void**)&ore,  g_ore);
    cudaGetSymbolAddress((void**)&oim,  g_oim);

    float* out_re = (float*)d_out;
    float* out_im = out_re + (size_t)BCT;

    dim3 blk(256);
    dim3 gproj(Tt / BT, Cc / BT, Bb);   // (16, 8, 8)
    dim3 gsc(Tt / BT, Tt / BT, Bb);     // (16, 16, 8)
    dim3 gsm(Tt, Bb);

    mixrot_kernel<<<gproj, blk>>>(Wq, phi_q, z_re, z_im, qre, qim);
    mixrot_kernel<<<gproj, blk>>>(Wk, phi_k, z_re, z_im, kre, kim);
    mixrot_kernel<<<gproj, blk>>>(Wv, phi_v, z_re, z_im, vre, vim);
    scores_kernel<<<gsc, blk>>>(qre, qim, kre, kim, attn);
    softmax_kernel<<<gsm, blk>>>(attn);
    av_kernel<<<gproj, blk>>>(vre, vim, attn, ore, oim);
    mixrot_kernel<<<gproj, blk>>>(Wo, phi_o, ore, oim, out_re, out_im);
}

// round 4
// speedup vs baseline: 1.1944x; 1.1260x over previous
#include <cuda_runtime.h>
#include <cuda_bf16.h>
#include <cstdint>
#include <math.h>

#define Bb 8
#define Cc 512
#define Tt 1024
#define BCT (Bb*Cc*Tt)
#define BTT (Bb*Tt*Tt)

__device__ float g_zreT[BCT], g_zimT[BCT];   // [b][t][c]
__device__ float g_qre[BCT], g_qim[BCT];     // [b][t][c]
__device__ float g_kre[BCT], g_kim[BCT];     // [b][t][c]
__device__ float g_vre[BCT], g_vim[BCT];     // [b][c][u]
__device__ float g_attn[BTT];                // [b][t][u]
__device__ float g_ore[BCT], g_oim[BCT];     // [b][t][c]

#define HDR 1024
#define SW128(o) ((o) ^ (((o) >> 3) & 0x70))

__device__ __forceinline__ uint32_t s2u(const void* p) {
    uint32_t a;
    asm("{ .reg .u64 t; cvta.to.shared.u64 t, %1; cvt.u32.u64 %0, t; }" : "=r"(a) : "l"(p));
    return a;
}
__device__ __forceinline__ uint32_t pk2(__nv_bfloat16 a, __nv_bfloat16 b) {
    return ((uint32_t)__bfloat16_as_ushort(b) << 16) | (uint32_t)__bfloat16_as_ushort(a);
}
// [nrow x 64] fp32 (row stride ld) -> hi/lo bf16 SW128 tiles (lo at +lo_off), 128B rows
__device__ __forceinline__ void ldcvt_tile(const float* __restrict__ g, int ld,
                                           char* sm_hi, int lo_off, int nrow, int tid) {
    char* sm_lo = sm_hi + lo_off;
    const int n4 = nrow * 16;
    for (int i = tid; i < n4; i += 256) {
        int r = i >> 4, c4 = (i & 15) << 2;
        float4 v = *(const float4*)(g + (size_t)r * ld + c4);
        __nv_bfloat16 h0 = __float2bfloat16(v.x), h1 = __float2bfloat16(v.y);
        __nv_bfloat16 h2 = __float2bfloat16(v.z), h3 = __float2bfloat16(v.w);
        __nv_bfloat16 l0 = __float2bfloat16(v.x - __bfloat162float(h0));
        __nv_bfloat16 l1 = __float2bfloat16(v.y - __bfloat162float(h1));
        __nv_bfloat16 l2 = __float2bfloat16(v.z - __bfloat162float(h2));
        __nv_bfloat16 l3 = __float2bfloat16(v.w - __bfloat162float(h3));
        uint32_t sw = SW128((uint32_t)(r * 128 + c4 * 2));
        *(uint2*)(sm_hi + sw) = make_uint2(pk2(h0, h1), pk2(h2, h3));
        *(uint2*)(sm_lo + sw) = make_uint2(pk2(l0, l1), pk2(l2, l3));
    }
}
__device__ __forceinline__ void ldsm4(uint32_t* r, uint32_t addr) {
    asm volatile("ldmatrix.sync.aligned.m8n8.x4.shared.b16 {%0,%1,%2,%3}, [%4];"
                 : "=r"(r[0]), "=r"(r[1]), "=r"(r[2]), "=r"(r[3]) : "r"(addr));
}
__device__ __forceinline__ void mma16816(float* d, const uint32_t* a, const uint32_t* b) {
    asm volatile(
        "mma.sync.aligned.m16n8k16.row.col.f32.bf16.bf16.f32 "
        "{%0,%1,%2,%3}, {%4,%5,%6,%7}, {%8,%9}, {%0,%1,%2,%3};"
        : "+f"(d[0]), "+f"(d[1]), "+f"(d[2]), "+f"(d[3])
        : "r"(a[0]), "r"(a[1]), "r"(a[2]), "r"(a[3]), "r"(b[0]), "r"(b[1]));
}
__device__ __forceinline__ void mma_split(float* d, const uint32_t* aH, const uint32_t* aL,
                                          const uint32_t* bH, const uint32_t* bL) {
    mma16816(d, aH, bH);
    mma16816(d, aH, bL);
    mma16816(d, aL, bH);
}
// A m16k16 fragment address in SW128 tile (rows x 128B)
__device__ __forceinline__ uint32_t a_addr(uint32_t base, int mbase, int ks, int lane) {
    int row = mbase + (lane & 15);
    int byt = ks * 32 + ((lane >> 4) << 4);
    return base + SW128((uint32_t)(row * 128 + byt));
}
// B: two n8k16 fragments (rows nbase..+15) in one x4
__device__ __forceinline__ uint32_t b_addr(uint32_t base, int nbase, int ks, int lane) {
    int row = nbase + ((lane >> 4) << 3) + (lane & 7);
    int byt = ks * 32 + (((lane >> 3) & 1) << 4);
    return base + SW128((uint32_t)(row * 128 + byt));
}

// ---------------------------------------------------------------------------
__global__ __launch_bounds__(256) void transpose_kernel(
    const float* __restrict__ re, const float* __restrict__ im,
    float* __restrict__ reT, float* __restrict__ imT)
{
    __shared__ float s0[32][33], s1[32][33];
    const int b = blockIdx.z, t0 = blockIdx.x * 32, c0 = blockIdx.y * 32;
    const float* pre = re + (size_t)b * Cc * Tt;
    const float* pim = im + (size_t)b * Cc * Tt;
    float* pT0 = reT + (size_t)b * Tt * Cc;
    float* pT1 = imT + (size_t)b * Tt * Cc;
    const int tx = threadIdx.x & 31, ty = threadIdx.x >> 5;
    #pragma unroll
    for (int i = 0; i < 4; i++) {
        int c = c0 + ty + i * 8;
        s0[ty + i * 8][tx] = pre[(size_t)c * Tt + t0 + tx];
        s1[ty + i * 8][tx] = pim[(size_t)c * Tt + t0 + tx];
    }
    __syncthreads();
    #pragma unroll
    for (int i = 0; i < 4; i++) {
        int t = t0 + ty + i * 8;
        pT0[(size_t)t * Cc + c0 + tx] = s0[tx][ty + i * 8];
        pT1[(size_t)t * Cc + c0 + tx] = s1[tx][ty + i * 8];
    }
}

// ---------------------------------------------------------------------------
// Q/K projection: D[t,d] = rot_col( zT[t,:]·W[d,:] ), dual A (re/im), single B (W)
// grid (Cc/64=8, Tt/128=8, B). smem: Are h/l, Aim h/l (128r), W h/l (64r)
// ---------------------------------------------------------------------------
#define QK_ARE (HDR)
#define QK_AIM (HDR + 32768)
#define QK_BW  (HDR + 65536)
#define QK_SM  (HDR + 81920)
__global__ __launch_bounds__(256) void gemm_qk(
    const float* __restrict__ zreT, const float* __restrict__ zimT,
    const float* __restrict__ W, const float* __restrict__ phi,
    float* __restrict__ Dre, float* __restrict__ Dim_)
{
    extern __shared__ char sm[];
    const uint32_t smb = s2u(sm);
    const int tid = threadIdx.x, wid = tid >> 5, lane = tid & 31;
    const int wm = wid & 3, wn = wid >> 2;
    const int b = blockIdx.z, m0 = blockIdx.y * 128, n0 = blockIdx.x * 64;

    float* cs = (float*)sm;
    float* sn = (float*)(sm + 256);
    if (tid < 64) {
        float s, c; sincosf(phi[n0 + tid], &s, &c);
        cs[tid] = c; sn[tid] = s;
    }

    const float* aRe = zreT + ((size_t)b * Tt + m0) * Cc;
    const float* aIm = zimT + ((size_t)b * Tt + m0) * Cc;
    const float* bW  = W + (size_t)n0 * Cc;

    float accR[2][4][4] = {}, accI[2][4][4] = {};

    for (int ch = 0; ch < 8; ch++) {
        const int k0 = ch * 64;
        ldcvt_tile(aRe + k0, Cc, sm + QK_ARE, 16384, 128, tid);
        ldcvt_tile(aIm + k0, Cc, sm + QK_AIM, 16384, 128, tid);
        ldcvt_tile(bW + k0, Cc, sm + QK_BW, 8192, 64, tid);
        __syncthreads();
        #pragma unroll
        for (int ks = 0; ks < 4; ks++) {
            uint32_t arH[2][4], arL[2][4], aiH[2][4], aiL[2][4];
            #pragma unroll
            for (int mi = 0; mi < 2; mi++) {
                ldsm4(arH[mi], a_addr(smb + QK_ARE,         wm * 32 + mi * 16, ks, lane));
                ldsm4(arL[mi], a_addr(smb + QK_ARE + 16384, wm * 32 + mi * 16, ks, lane));
                ldsm4(aiH[mi], a_addr(smb + QK_AIM,         wm * 32 + mi * 16, ks, lane));
                ldsm4(aiL[mi], a_addr(smb + QK_AIM + 16384, wm * 32 + mi * 16, ks, lane));
            }
            uint32_t bH[8], bL[8];
            ldsm4(bH + 0, b_addr(smb + QK_BW,        wn * 32,      ks, lane));
            ldsm4(bH + 4, b_addr(smb + QK_BW,        wn * 32 + 16, ks, lane));
            ldsm4(bL + 0, b_addr(smb + QK_BW + 8192, wn * 32,      ks, lane));
            ldsm4(bL + 4, b_addr(smb + QK_BW + 8192, wn * 32 + 16, ks, lane));
            #pragma unroll
            for (int mi = 0; mi < 2; mi++)
                #pragma unroll
                for (int nf = 0; nf < 4; nf++) {
                    mma_split(accR[mi][nf], arH[mi], arL[mi], bH + nf * 2, bL + nf * 2);
                    mma_split(accI[mi][nf], aiH[mi], aiL[mi], bH + nf * 2, bL + nf * 2);
                }
        }
        __syncthreads();
    }

    float* dre = Dre + (size_t)b * Tt * Cc;
    float* dim = Dim_ + (size_t)b * Tt * Cc;
    const int g = lane >> 2, cp = (lane & 3) * 2;
    #pragma unroll
    for (int mi = 0; mi < 2; mi++) {
        const int r0 = m0 + wm * 32 + mi * 16 + g;
        #pragma unroll
        for (int nf = 0; nf < 4; nf++) {
            const int c = wn * 32 + nf * 8 + cp;
            float c0 = cs[c], s0 = sn[c], c1 = cs[c + 1], s1 = sn[c + 1];
            float* aR = accR[mi][nf];
            float* aI = accI[mi][nf];
            *(float2*)&dre[(size_t)r0 * Cc + n0 + c]       = make_float2(aR[0]*c0 - aI[0]*s0, aR[1]*c1 - aI[1]*s1);
            *(float2*)&dim[(size_t)r0 * Cc + n0 + c]       = make_float2(aR[0]*s0 + aI[0]*c0, aR[1]*s1 + aI[1]*c1);
            *(float2*)&dre[(size_t)(r0 + 8) * Cc + n0 + c] = make_float2(aR[2]*c0 - aI[2]*s0, aR[3]*c1 - aI[3]*s1);
            *(float2*)&dim[(size_t)(r0 + 8) * Cc + n0 + c] = make_float2(aR[2]*s0 + aI[2]*c0, aR[3]*s1 + aI[3]*c1);
        }
    }
}

// ---------------------------------------------------------------------------
// wB (V and O projections): D[d,t] = rot_row( W[d,:]·B{re,im}[t,:] )
// single A (W, 128 rows), dual B (64 rows). grid (Tt/64=16, Cc/128=4, B)
// ---------------------------------------------------------------------------
#define WB_AW  (HDR)
#define WB_BRE (HDR + 32768)
#define WB_BIM (HDR + 49152)
#define WB_SM  (HDR + 65536)
__global__ __launch_bounds__(256) void gemm_wB(
    const float* __restrict__ W, const float* __restrict__ phi,
    const float* __restrict__ Bre, const float* __restrict__ Bim,
    float* __restrict__ Dre, float* __restrict__ Dim_)
{
    extern __shared__ char sm[];
    const uint32_t smb = s2u(sm);
    const int tid = threadIdx.x, wid = tid >> 5, lane = tid & 31;
    const int wm = wid & 3, wn = wid >> 2;
    const int b = blockIdx.z, m0 = blockIdx.y * 128, n0 = blockIdx.x * 64;

    float* cs = (float*)sm;
    float* sn = (float*)(sm + 512);
    if (tid < 128) {
        float s, c; sincosf(phi[m0 + tid], &s, &c);
        cs[tid] = c; sn[tid] = s;
    }

    const float* aW = W + (size_t)m0 * Cc;
    const float* bR = Bre + ((size_t)b * Tt + n0) * Cc;
    const float* bI = Bim + ((size_t)b * Tt + n0) * Cc;

    float accR[2][4][4] = {}, accI[2][4][4] = {};

    for (int ch = 0; ch < 8; ch++) {
        const int k0 = ch * 64;
        ldcvt_tile(aW + k0, Cc, sm + WB_AW, 16384, 128, tid);
        ldcvt_tile(bR + k0, Cc, sm + WB_BRE, 8192, 64, tid);
        ldcvt_tile(bI + k0, Cc, sm + WB_BIM, 8192, 64, tid);
        __syncthreads();
        #pragma unroll
        for (int ks = 0; ks < 4; ks++) {
            uint32_t aH[2][4], aL[2][4];
            #pragma unroll
            for (int mi = 0; mi < 2; mi++) {
                ldsm4(aH[mi], a_addr(smb + WB_AW,         wm * 32 + mi * 16, ks, lane));
                ldsm4(aL[mi], a_addr(smb + WB_AW + 16384, wm * 32 + mi * 16, ks, lane));
            }
            uint32_t rH[8], rL[8], iH[8], iL[8];
            ldsm4(rH + 0, b_addr(smb + WB_BRE,        wn * 32,      ks, lane));
            ldsm4(rH + 4, b_addr(smb + WB_BRE,        wn * 32 + 16, ks, lane));
            ldsm4(rL + 0, b_addr(smb + WB_BRE + 8192, wn * 32,      ks, lane));
            ldsm4(rL + 4, b_addr(smb + WB_BRE + 8192, wn * 32 + 16, ks, lane));
            ldsm4(iH + 0, b_addr(smb + WB_BIM,        wn * 32,      ks, lane));
            ldsm4(iH + 4, b_addr(smb + WB_BIM,        wn * 32 + 16, ks, lane));
            ldsm4(iL + 0, b_addr(smb + WB_BIM + 8192, wn * 32,      ks, lane));
            ldsm4(iL + 4, b_addr(smb + WB_BIM + 8192, wn * 32 + 16, ks, lane));
            #pragma unroll
            for (int mi = 0; mi < 2; mi++)
                #pragma unroll
                for (int nf = 0; nf < 4; nf++) {
                    mma_split(accR[mi][nf], aH[mi], aL[mi], rH + nf * 2, rL + nf * 2);
                    mma_split(accI[mi][nf], aH[mi], aL[mi], iH + nf * 2, iL + nf * 2);
                }
        }
        __syncthreads();
    }

    float* dre = Dre + (size_t)b * Cc * Tt;
    float* dim = Dim_ + (size_t)b * Cc * Tt;
    const int g = lane >> 2, cp = (lane & 3) * 2;
    #pragma unroll
    for (int mi = 0; mi < 2; mi++) {
        const int lr = wm * 32 + mi * 16 + g;
        const float c0 = cs[lr], s0 = sn[lr], c8 = cs[lr + 8], s8 = sn[lr + 8];
        const int r0 = m0 + lr;
        #pragma unroll
        for (int nf = 0; nf < 4; nf++) {
            const int c = wn * 32 + nf * 8 + cp;
            float* aR = accR[mi][nf];
            float* aI = accI[mi][nf];
            *(float2*)&dre[(size_t)r0 * Tt + n0 + c]       = make_float2(aR[0]*c0 - aI[0]*s0, aR[1]*c0 - aI[1]*s0);
            *(float2*)&dim[(size_t)r0 * Tt + n0 + c]       = make_float2(aR[0]*s0 + aI[0]*c0, aR[1]*s0 + aI[1]*c0);
            *(float2*)&dre[(size_t)(r0 + 8) * Tt + n0 + c] = make_float2(aR[2]*c8 - aI[2]*s8, aR[3]*c8 - aI[3]*s8);
            *(float2*)&dim[(size_t)(r0 + 8) * Tt + n0 + c] = make_float2(aR[2]*s8 + aI[2]*c8, aR[3]*s8 + aI[3]*c8);
        }
    }
}

// ---------------------------------------------------------------------------
// scores: S[t,u] = (Q·Kᵀ re + im)/8, causal. dual A (q), dual B (k), single acc.
// grid (Tt/64=16, Tt/128=8, B)
// ---------------------------------------------------------------------------
#define SC_QRE (HDR)
#define SC_QIM (HDR + 32768)
#define SC_KRE (HDR + 65536)
#define SC_KIM (HDR + 81920)
#define SC_SM  (HDR + 98304)
__global__ __launch_bounds__(256) void gemm_scores(
    const float* __restrict__ Qre, const float* __restrict__ Qim,
    const float* __restrict__ Kre, const float* __restrict__ Kim,
    float* __restrict__ attn)
{
    extern __shared__ char sm[];
    const uint32_t smb = s2u(sm);
    const int tid = threadIdx.x, wid = tid >> 5, lane = tid & 31;
    const int wm = wid & 3, wn = wid >> 2;
    const int b = blockIdx.z, m0 = blockIdx.y * 128, n0 = blockIdx.x * 64;
    float* arow = attn + (size_t)b * Tt * Tt;
    const float ni = __int_as_float(0xff800000);

    if (n0 >= m0 + 128) {
        float4 v = make_float4(ni, ni, ni, ni);
        for (int i = tid; i < 128 * 16; i += 256) {
            int r = i >> 4, c4 = (i & 15) << 2;
            *(float4*)&arow[(size_t)(m0 + r) * Tt + n0 + c4] = v;
        }
        return;
    }

    const float* qR = Qre + ((size_t)b * Tt + m0) * Cc;
    const float* qI = Qim + ((size_t)b * Tt + m0) * Cc;
    const float* kR = Kre + ((size_t)b * Tt + n0) * Cc;
    const float* kI = Kim + ((size_t)b * Tt + n0) * Cc;

    float acc[2][4][4] = {};

    for (int ch = 0; ch < 8; ch++) {
        const int k0 = ch * 64;
        ldcvt_tile(qR + k0, Cc, sm + SC_QRE, 16384, 128, tid);
        ldcvt_tile(qI + k0, Cc, sm + SC_QIM, 16384, 128, tid);
        ldcvt_tile(kR + k0, Cc, sm + SC_KRE, 8192, 64, tid);
        ldcvt_tile(kI + k0, Cc, sm + SC_KIM, 8192, 64, tid);
        __syncthreads();
        #pragma unroll
        for (int ks = 0; ks < 4; ks++) {
            uint32_t qrH[2][4], qrL[2][4], qiH[2][4], qiL[2][4];
            #pragma unroll
            for (int mi = 0; mi < 2; mi++) {
                ldsm4(qrH[mi], a_addr(smb + SC_QRE,         wm * 32 + mi * 16, ks, lane));
                ldsm4(qrL[mi], a_addr(smb + SC_QRE + 16384, wm * 32 + mi * 16, ks, lane));
                ldsm4(qiH[mi], a_addr(smb + SC_QIM,         wm * 32 + mi * 16, ks, lane));
                ldsm4(qiL[mi], a_addr(smb + SC_QIM + 16384, wm * 32 + mi * 16, ks, lane));
            }
            uint32_t rH[8], rL[8], iH[8], iL[8];
            ldsm4(rH + 0, b_addr(smb + SC_KRE,        wn * 32,      ks, lane));
            ldsm4(rH + 4, b_addr(smb + SC_KRE,        wn * 32 + 16, ks, lane));
            ldsm4(rL + 0, b_addr(smb + SC_KRE + 8192, wn * 32,      ks, lane));
            ldsm4(rL + 4, b_addr(smb + SC_KRE + 8192, wn * 32 + 16, ks, lane));
            ldsm4(iH + 0, b_addr(smb + SC_KIM,        wn * 32,      ks, lane));
            ldsm4(iH + 4, b_addr(smb + SC_KIM,        wn * 32 + 16, ks, lane));
            ldsm4(iL + 0, b_addr(smb + SC_KIM + 8192, wn * 32,      ks, lane));
            ldsm4(iL + 4, b_addr(smb + SC_KIM + 8192, wn * 32 + 16, ks, lane));
            #pragma unroll
            for (int mi = 0; mi < 2; mi++)
                #pragma unroll
                for (int nf = 0; nf < 4; nf++) {
                    mma_split(acc[mi][nf], qrH[mi], qrL[mi], rH + nf * 2, rL + nf * 2);
                    mma_split(acc[mi][nf], qiH[mi], qiL[mi], iH + nf * 2, iL + nf * 2);
                }
        }
        __syncthreads();
    }

    const int g = lane >> 2, cp = (lane & 3) * 2;
    #pragma unroll
    for (int mi = 0; mi < 2; mi++) {
        const int r0 = m0 + wm * 32 + mi * 16 + g;
        #pragma unroll
        for (int nf = 0; nf < 4; nf++) {
            const int u = n0 + wn * 32 + nf * 8 + cp;
            float* a = acc[mi][nf];
            float2 v0, v1;
            v0.x = (u     > r0) ? ni : a[0] * 0.125f;
            v0.y = (u + 1 > r0) ? ni : a[1] * 0.125f;
            v1.x = (u     > r0 + 8) ? ni : a[2] * 0.125f;
            v1.y = (u + 1 > r0 + 8) ? ni : a[3] * 0.125f;
            *(float2*)&arow[(size_t)r0 * Tt + u]       = v0;
            *(float2*)&arow[(size_t)(r0 + 8) * Tt + u] = v1;
        }
    }
}

// ---------------------------------------------------------------------------
__global__ __launch_bounds__(256) void softmax_kernel(float* __restrict__ attn)
{
    const int t = blockIdx.x, b = blockIdx.y;
    float* row = attn + ((size_t)b * Tt + t) * Tt;
    const int tid = threadIdx.x;
    float4 v = ((const float4*)row)[tid];
    float m = fmaxf(fmaxf(v.x, v.y), fmaxf(v.z, v.w));
    __shared__ float red[8];
    #pragma unroll
    for (int o = 16; o > 0; o >>= 1) m = fmaxf(m, __shfl_xor_sync(0xffffffffu, m, o));
    if ((tid & 31) == 0) red[tid >> 5] = m;
    __syncthreads();
    if (tid == 0) {
        float mm = red[0];
        #pragma unroll
        for (int i = 1; i < 8; i++) mm = fmaxf(mm, red[i]);
        red[0] = mm;
    }
    __syncthreads();
    m = red[0];
    __syncthreads();
    float e0 = expf(v.x - m), e1 = expf(v.y - m), e2 = expf(v.z - m), e3 = expf(v.w - m);
    float s = e0 + e1 + e2 + e3;
    #pragma unroll
    for (int o = 16; o > 0; o >>= 1) s += __shfl_xor_sync(0xffffffffu, s, o);
    if ((tid & 31) == 0) red[tid >> 5] = s;
    __syncthreads();
    if (tid == 0) {
        float ss = 0.f;
        #pragma unroll
        for (int i = 0; i < 8; i++) ss += red[i];
        red[0] = ss;
    }
    __syncthreads();
    const float inv = 1.0f / red[0];
    ((float4*)row)[tid] = make_float4(e0 * inv, e1 * inv, e2 * inv, e3 * inv);
}

// ---------------------------------------------------------------------------
// AV: O[t,c] = attn[t,:]·V[c,:] (dual B = v re/im). K bounded causally.
// grid (Cc/64=8, Tt/128=8, B)
// ---------------------------------------------------------------------------
#define AV_AT  (HDR)
#define AV_VRE (HDR + 32768)
#define AV_VIM (HDR + 49152)
#define AV_SM  (HDR + 65536)
__global__ __launch_bounds__(256) void gemm_av(
    const float* __restrict__ attn,
    const float* __restrict__ Vre, const float* __restrict__ Vim,
    float* __restrict__ Ore, float* __restrict__ Oim)
{
    extern __shared__ char sm[];
    const uint32_t smb = s2u(sm);
    const int tid = threadIdx.x, wid = tid >> 5, lane = tid & 31;
    const int wm = wid & 3, wn = wid >> 2;
    const int b = blockIdx.z, m0 = blockIdx.y * 128, n0 = blockIdx.x * 64;

    const float* aA = attn + ((size_t)b * Tt + m0) * Tt;
    const float* vR = Vre + ((size_t)b * Cc + n0) * Tt;
    const float* vI = Vim + ((size_t)b * Cc + n0) * Tt;

    float accR[2][4][4] = {}, accI[2][4][4] = {};

    const int nch = m0 / 64 + 2;
    for (int ch = 0; ch < nch; ch++) {
        const int k0 = ch * 64;
        ldcvt_tile(aA + k0, Tt, sm + AV_AT, 16384, 128, tid);
        ldcvt_tile(vR + k0, Tt, sm + AV_VRE, 8192, 64, tid);
        ldcvt_tile(vI + k0, Tt, sm + AV_VIM, 8192, 64, tid);
        __syncthreads();
        #pragma unroll
        for (int ks = 0; ks < 4; ks++) {
            uint32_t aH[2][4], aL[2][4];
            #pragma unroll
            for (int mi = 0; mi < 2; mi++) {
                ldsm4(aH[mi], a_addr(smb + AV_AT,         wm * 32 + mi * 16, ks, lane));
                ldsm4(aL[mi], a_addr(smb + AV_AT + 16384, wm * 32 + mi * 16, ks, lane));
            }
            uint32_t rH[8], rL[8], iH[8], iL[8];
            ldsm4(rH + 0, b_addr(smb + AV_VRE,        wn * 32,      ks, lane));
            ldsm4(rH + 4, b_addr(smb + AV_VRE,        wn * 32 + 16, ks, lane));
            ldsm4(rL + 0, b_addr(smb + AV_VRE + 8192, wn * 32,      ks, lane));
            ldsm4(rL + 4, b_addr(smb + AV_VRE + 8192, wn * 32 + 16, ks, lane));
            ldsm4(iH + 0, b_addr(smb + AV_VIM,        wn * 32,      ks, lane));
            ldsm4(iH + 4, b_addr(smb + AV_VIM,        wn * 32 + 16, ks, lane));
            ldsm4(iL + 0, b_addr(smb + AV_VIM + 8192, wn * 32,      ks, lane));
            ldsm4(iL + 4, b_addr(smb + AV_VIM + 8192, wn * 32 + 16, ks, lane));
            #pragma unroll
            for (int mi = 0; mi < 2; mi++)
                #pragma unroll
                for (int nf = 0; nf < 4; nf++) {
                    mma_split(accR[mi][nf], aH[mi], aL[mi], rH + nf * 2, rL + nf * 2);
                    mma_split(accI[mi][nf], aH[mi], aL[mi], iH + nf * 2, iL + nf * 2);
                }
        }
        __syncthreads();
    }

    float* ore = Ore + (size_t)b * Tt * Cc;
    float* oim = Oim + (size_t)b * Tt * Cc;
    const int g = lane >> 2, cp = (lane & 3) * 2;
    #pragma unroll
    for (int mi = 0; mi < 2; mi++) {
        const int r0 = m0 + wm * 32 + mi * 16 + g;
        #pragma unroll
        for (int nf = 0; nf < 4; nf++) {
            const int c = n0 + wn * 32 + nf * 8 + cp;
            float* aR = accR[mi][nf];
            float* aI = accI[mi][nf];
            *(float2*)&ore[(size_t)r0 * Cc + c]       = make_float2(aR[0], aR[1]);
            *(float2*)&oim[(size_t)r0 * Cc + c]       = make_float2(aI[0], aI[1]);
            *(float2*)&ore[(size_t)(r0 + 8) * Cc + c] = make_float2(aR[2], aR[3]);
            *(float2*)&oim[(size_t)(r0 + 8) * Cc + c] = make_float2(aI[2], aI[3]);
        }
    }
}

// ---------------------------------------------------------------------------
extern "C" void kernel_launch(void* const* d_in, const int* in_sizes, int n_in,
                              void* d_out, int out_size)
{
    const float* z_re  = (const float*)d_in[0];
    const float* z_im  = (const float*)d_in[1];
    const float* Wq    = (const float*)d_in[2];
    const float* phi_q = (const float*)d_in[3];
    const float* Wk    = (const float*)d_in[4];
    const float* phi_k = (const float*)d_in[5];
    const float* Wv    = (const float*)d_in[6];
    const float* phi_v = (const float*)d_in[7];
    const float* Wo    = (const float*)d_in[8];
    const float* phi_o = (const float*)d_in[9];

    float *zreT, *zimT, *qre, *qim, *kre, *kim, *vre, *vim, *attn, *ore, *oim;
    cudaGetSymbolAddress((void**)&zreT, g_zreT);
    cudaGetSymbolAddress((void**)&zimT, g_zimT);
    cudaGetSymbolAddress((void**)&qre,  g_qre);
    cudaGetSymbolAddress((void**)&qim,  g_qim);
    cudaGetSymbolAddress((void**)&kre,  g_kre);
    cudaGetSymbolAddress((void**)&kim,  g_kim);
    cudaGetSymbolAddress((void**)&vre,  g_vre);
    cudaGetSymbolAddress((void**)&vim,  g_vim);
    cudaGetSymbolAddress((void**)&attn, g_attn);
    cudaGetSymbolAddress((void**)&ore,  g_ore);
    cudaGetSymbolAddress((void**)&oim,  g_oim);

    cudaFuncSetAttribute(gemm_qk,     cudaFuncAttributeMaxDynamicSharedMemorySize, QK_SM);
    cudaFuncSetAttribute(gemm_wB,     cudaFuncAttributeMaxDynamicSharedMemorySize, WB_SM);
    cudaFuncSetAttribute(gemm_scores, cudaFuncAttributeMaxDynamicSharedMemorySize, SC_SM);
    cudaFuncSetAttribute(gemm_av,     cudaFuncAttributeMaxDynamicSharedMemorySize, AV_SM);

    float* out_re = (float*)d_out;
    float* out_im = out_re + (size_t)BCT;

    dim3 blk(256);
    transpose_kernel<<<dim3(32, 16, Bb), blk>>>(z_re, z_im, zreT, zimT);
    gemm_qk<<<dim3(8, 8, Bb), blk, QK_SM>>>(zreT, zimT, Wq, phi_q, qre, qim);
    gemm_qk<<<dim3(8, 8, Bb), blk, QK_SM>>>(zreT, zimT, Wk, phi_k, kre, kim);
    gemm_wB<<<dim3(16, 4, Bb), blk, WB_SM>>>(Wv, phi_v, zreT, zimT, vre, vim);
    gemm_scores<<<dim3(16, 8, Bb), blk, SC_SM>>>(qre, qim, kre, kim, attn);
    softmax_kernel<<<dim3(Tt, Bb), blk>>>(attn);
    gemm_av<<<dim3(8, 8, Bb), blk, AV_SM>>>(attn, vre, vim, ore, oim);
    gemm_wB<<<dim3(16, 4, Bb), blk, WB_SM>>>(Wo, phi_o, ore, oim, out_re, out_im);
}

// round 5
// speedup vs baseline: 2.3571x; 1.9735x over previous
#include <cuda_runtime.h>
#include <cuda_bf16.h>
#include <cstdint>
#include <math.h>

#define Bb 8
#define Cc 512
#define Tt 1024
#define BCT (Bb*Cc*Tt)
#define BTT (Bb*Tt*Tt)

// chunked bf16 tensor layout: [ch][R rows][128B], swizzled per-row:
// byte(col,row) = (col*2) ^ ((row&7)<<4)
#define ZB (8*1024*128)     // z/q/k/o per-batch bytes (8 chunks x 1024 rows)
#define VB (16*512*128)     // v per-batch (16 chunks x 512 rows)
#define AB (16*1024*128)    // attn bf16 per-batch (16 chunks x 1024 rows)
#define WBY (8*512*128)     // one W matrix (8 chunks x 512 rows)

__device__ __align__(16) unsigned char g_zreh[Bb*ZB], g_zrel[Bb*ZB], g_zimh[Bb*ZB], g_ziml[Bb*ZB];
__device__ __align__(16) unsigned char g_qreh[Bb*ZB], g_qrel[Bb*ZB], g_qimh[Bb*ZB], g_qiml[Bb*ZB];
__device__ __align__(16) unsigned char g_kreh[Bb*ZB], g_krel[Bb*ZB], g_kimh[Bb*ZB], g_kiml[Bb*ZB];
__device__ __align__(16) unsigned char g_vreh[Bb*VB], g_vrel[Bb*VB], g_vimh[Bb*VB], g_viml[Bb*VB];
__device__ __align__(16) unsigned char g_ath[Bb*AB],  g_atl[Bb*AB];
__device__ __align__(16) unsigned char g_oreh[Bb*ZB], g_orel[Bb*ZB], g_oimh[Bb*ZB], g_oiml[Bb*ZB];
__device__ __align__(16) unsigned char g_wh[4*WBY],   g_wl[4*WBY];
__device__ float g_attn[BTT];

#define SW128(o) ((o) ^ (((o) >> 3) & 0x70))

__device__ __forceinline__ uint32_t s2u(const void* p) {
    uint32_t a;
    asm("{ .reg .u64 t; cvta.to.shared.u64 t, %1; cvt.u32.u64 %0, t; }" : "=r"(a) : "l"(p));
    return a;
}
__device__ __forceinline__ uint32_t pk2(__nv_bfloat16 a, __nv_bfloat16 b) {
    return ((uint32_t)__bfloat16_as_ushort(b) << 16) | (uint32_t)__bfloat16_as_ushort(a);
}
// write a hi/lo bf16 pair (cols col,col+1) to a chunked tensor
__device__ __forceinline__ void st_pair(unsigned char* bh, unsigned char* bl,
                                        int R, int ch, int row, int col, float v0, float v1) {
    size_t off = (((size_t)ch * R + row) << 7) + (uint32_t)((col * 2) ^ ((row & 7) << 4));
    __nv_bfloat16 h0 = __float2bfloat16(v0), h1 = __float2bfloat16(v1);
    *(uint32_t*)(bh + off) = pk2(h0, h1);
    __nv_bfloat16 l0 = __float2bfloat16(v0 - __bfloat162float(h0));
    __nv_bfloat16 l1 = __float2bfloat16(v1 - __bfloat162float(h1));
    *(uint32_t*)(bl + off) = pk2(l0, l1);
}
__device__ __forceinline__ void cpa16(uint32_t s, const void* g) {
    asm volatile("cp.async.cg.shared.global [%0], [%1], 16;" :: "r"(s), "l"(g) : "memory");
}
__device__ __forceinline__ void cpa_commit() { asm volatile("cp.async.commit_group;" ::: "memory"); }
__device__ __forceinline__ void cpa_wait1()  { asm volatile("cp.async.wait_group 1;" ::: "memory"); }
__device__ __forceinline__ void cpa_wait0()  { asm volatile("cp.async.wait_group 0;" ::: "memory"); }
__device__ __forceinline__ void cpreg(uint32_t s, const unsigned char* g, int nbytes, int tid) {
    for (int o = tid * 16; o < nbytes; o += 4096) cpa16(s + o, g + o);
}
__device__ __forceinline__ void ldsm4(uint32_t* r, uint32_t addr) {
    asm volatile("ldmatrix.sync.aligned.m8n8.x4.shared.b16 {%0,%1,%2,%3}, [%4];"
                 : "=r"(r[0]), "=r"(r[1]), "=r"(r[2]), "=r"(r[3]) : "r"(addr));
}
__device__ __forceinline__ void mma16816(float* d, const uint32_t* a, const uint32_t* b) {
    asm volatile(
        "mma.sync.aligned.m16n8k16.row.col.f32.bf16.bf16.f32 "
        "{%0,%1,%2,%3}, {%4,%5,%6,%7}, {%8,%9}, {%0,%1,%2,%3};"
        : "+f"(d[0]), "+f"(d[1]), "+f"(d[2]), "+f"(d[3])
        : "r"(a[0]), "r"(a[1]), "r"(a[2]), "r"(a[3]), "r"(b[0]), "r"(b[1]));
}
__device__ __forceinline__ void mma_split(float* d, const uint32_t* aH, const uint32_t* aL,
                                          const uint32_t* bH, const uint32_t* bL) {
    mma16816(d, aH, bH);
    mma16816(d, aH, bL);
    mma16816(d, aL, bH);
}
__device__ __forceinline__ uint32_t a_addr(uint32_t base, int mbase, int ks, int lane) {
    int row = mbase + (lane & 15);
    int byt = ks * 32 + ((lane >> 4) << 4);
    return base + SW128((uint32_t)(row * 128 + byt));
}
__device__ __forceinline__ uint32_t b_addr(uint32_t base, int nbase, int ks, int lane) {
    int row = nbase + ((lane >> 4) << 3) + (lane & 7);
    int byt = ks * 32 + (((lane >> 3) & 1) << 4);
    return base + SW128((uint32_t)(row * 128 + byt));
}

// ---------------------------------------------------------------------------
// prep_z: fp32 z[b][c][t] -> chunked bf16 hi/lo [b][c/64][t][128B] (transpose)
// grid (Tt/32=32, Cc/64=8, Bb), block 256
// ---------------------------------------------------------------------------
__global__ __launch_bounds__(256) void prep_z(
    const float* __restrict__ zre, const float* __restrict__ zim)
{
    __shared__ float sre[64][33], sim[64][33];
    const int b = blockIdx.z, t0 = blockIdx.x * 32, c0 = blockIdx.y * 64;
    const int tid = threadIdx.x;
    const float* pre = zre + (size_t)b * Cc * Tt;
    const float* pim = zim + (size_t)b * Cc * Tt;
    for (int i = tid; i < 2048; i += 256) {
        int cl = i >> 5, tl = i & 31;
        sre[cl][tl] = pre[(size_t)(c0 + cl) * Tt + t0 + tl];
        sim[cl][tl] = pim[(size_t)(c0 + cl) * Tt + t0 + tl];
    }
    __syncthreads();
    unsigned char* zrh = g_zreh + (size_t)b * ZB;
    unsigned char* zrl = g_zrel + (size_t)b * ZB;
    unsigned char* zih = g_zimh + (size_t)b * ZB;
    unsigned char* zil = g_ziml + (size_t)b * ZB;
    const int ch = c0 >> 6;
    for (int i = tid; i < 1024; i += 256) {
        int tl = i >> 5, p = i & 31;
        int t = t0 + tl, col = p * 2;
        st_pair(zrh, zrl, 1024, ch, t, col, sre[col][tl], sre[col + 1][tl]);
        st_pair(zih, zil, 1024, ch, t, col, sim[col][tl], sim[col + 1][tl]);
    }
}

// ---------------------------------------------------------------------------
// prep_w: fp32 W[d][c] -> chunked bf16 hi/lo [c/64][d][128B]. grid (8, 4)
// ---------------------------------------------------------------------------
__global__ __launch_bounds__(256) void prep_w(
    const float* __restrict__ W0, const float* __restrict__ W1,
    const float* __restrict__ W2, const float* __restrict__ W3)
{
    const int d0 = blockIdx.x * 64, wi = blockIdx.y, tid = threadIdx.x;
    const float* W = (wi == 0) ? W0 : (wi == 1) ? W1 : (wi == 2) ? W2 : W3;
    unsigned char* oh = g_wh + (size_t)wi * WBY;
    unsigned char* ol = g_wl + (size_t)wi * WBY;
    for (int i = tid; i < 8192; i += 256) {
        int dl = i >> 7, q = i & 127;
        int c = q * 4, d = d0 + dl;
        float4 v = *(const float4*)&W[(size_t)d * Cc + c];
        st_pair(oh, ol, 512, c >> 6, d, c & 63, v.x, v.y);
        st_pair(oh, ol, 512, c >> 6, d, (c & 63) + 2, v.z, v.w);
    }
}

// ---------------------------------------------------------------------------
// gemm_qk: D[t,d] = rot_col( zT·W ). A dual (zre/zim 128 rows), B single (W 64).
// out: q or k chunked bf16. grid (Cc/64=8, Tt/128=8, Bb). smem 2x81920.
// ---------------------------------------------------------------------------
#define QK_STRIDE 81920
#define QK_SM (2*QK_STRIDE)
__global__ __launch_bounds__(256) void gemm_qk(
    const unsigned char* __restrict__ wh, const unsigned char* __restrict__ wl,
    const float* __restrict__ phi,
    unsigned char* __restrict__ dreh, unsigned char* __restrict__ drel,
    unsigned char* __restrict__ dimh, unsigned char* __restrict__ diml)
{
    extern __shared__ char sm[];
    __shared__ float s_cs[64], s_sn[64];
    const uint32_t smb = s2u(sm);
    const int tid = threadIdx.x, wid = tid >> 5, lane = tid & 31;
    const int wm = wid & 3, wn = wid >> 2;
    const int b = blockIdx.z, m0 = blockIdx.y * 128, n0 = blockIdx.x * 64;

    if (tid < 64) {
        float s, c; sincosf(phi[n0 + tid], &s, &c);
        s_cs[tid] = c; s_sn[tid] = s;
    }

    const unsigned char* zrh = g_zreh + (size_t)b * ZB;
    const unsigned char* zrl = g_zrel + (size_t)b * ZB;
    const unsigned char* zih = g_zimh + (size_t)b * ZB;
    const unsigned char* zil = g_ziml + (size_t)b * ZB;

    auto issue = [&](int ch, uint32_t bs) {
        size_t ao = ((size_t)(ch * 1024 + m0)) << 7;
        size_t bo = ((size_t)(ch * 512 + n0)) << 7;
        cpreg(bs + 0,     zrh + ao, 16384, tid);
        cpreg(bs + 16384, zrl + ao, 16384, tid);
        cpreg(bs + 32768, zih + ao, 16384, tid);
        cpreg(bs + 49152, zil + ao, 16384, tid);
        cpreg(bs + 65536, wh + bo, 8192, tid);
        cpreg(bs + 73728, wl + bo, 8192, tid);
    };

    float accR[2][4][4] = {}, accI[2][4][4] = {};
    issue(0, smb); cpa_commit();
    for (int ch = 0; ch < 8; ch++) {
        uint32_t base = smb + (ch & 1) * QK_STRIDE;
        if (ch + 1 < 8) { issue(ch + 1, smb + ((ch + 1) & 1) * QK_STRIDE); cpa_commit(); cpa_wait1(); }
        else cpa_wait0();
        __syncthreads();
        #pragma unroll
        for (int ks = 0; ks < 4; ks++) {
            uint32_t arH[2][4], arL[2][4], aiH[2][4], aiL[2][4];
            #pragma unroll
            for (int mi = 0; mi < 2; mi++) {
                ldsm4(arH[mi], a_addr(base + 0,     wm * 32 + mi * 16, ks, lane));
                ldsm4(arL[mi], a_addr(base + 16384, wm * 32 + mi * 16, ks, lane));
                ldsm4(aiH[mi], a_addr(base + 32768, wm * 32 + mi * 16, ks, lane));
                ldsm4(aiL[mi], a_addr(base + 49152, wm * 32 + mi * 16, ks, lane));
            }
            uint32_t bH[8], bL[8];
            ldsm4(bH + 0, b_addr(base + 65536, wn * 32,      ks, lane));
            ldsm4(bH + 4, b_addr(base + 65536, wn * 32 + 16, ks, lane));
            ldsm4(bL + 0, b_addr(base + 73728, wn * 32,      ks, lane));
            ldsm4(bL + 4, b_addr(base + 73728, wn * 32 + 16, ks, lane));
            #pragma unroll
            for (int mi = 0; mi < 2; mi++)
                #pragma unroll
                for (int nf = 0; nf < 4; nf++) {
                    mma_split(accR[mi][nf], arH[mi], arL[mi], bH + nf * 2, bL + nf * 2);
                    mma_split(accI[mi][nf], aiH[mi], aiL[mi], bH + nf * 2, bL + nf * 2);
                }
        }
        __syncthreads();
    }

    unsigned char* qrh = dreh + (size_t)b * ZB;
    unsigned char* qrl = drel + (size_t)b * ZB;
    unsigned char* qih = dimh + (size_t)b * ZB;
    unsigned char* qil = diml + (size_t)b * ZB;
    const int g = lane >> 2, cp = (lane & 3) * 2, och = n0 >> 6;
    #pragma unroll
    for (int mi = 0; mi < 2; mi++) {
        const int r0 = m0 + wm * 32 + mi * 16 + g;
        #pragma unroll
        for (int nf = 0; nf < 4; nf++) {
            const int c = wn * 32 + nf * 8 + cp;
            float c0 = s_cs[c], s0 = s_sn[c], c1 = s_cs[c + 1], s1 = s_sn[c + 1];
            float* aR = accR[mi][nf];
            float* aI = accI[mi][nf];
            st_pair(qrh, qrl, 1024, och, r0, c, aR[0]*c0 - aI[0]*s0, aR[1]*c1 - aI[1]*s1);
            st_pair(qih, qil, 1024, och, r0, c, aR[0]*s0 + aI[0]*c0, aR[1]*s1 + aI[1]*c1);
            st_pair(qrh, qrl, 1024, och, r0 + 8, c, aR[2]*c0 - aI[2]*s0, aR[3]*c1 - aI[3]*s1);
            st_pair(qih, qil, 1024, och, r0 + 8, c, aR[2]*s0 + aI[2]*c0, aR[3]*s1 + aI[3]*c1);
        }
    }
}

// ---------------------------------------------------------------------------
// gemm_wB: D[d,n] = rot_row( W·B{re,im}ᵀ ). A = W (128 rows), B dual (64 rows).
// BF16OUT: write chunked bf16 (V). else: fp32 strided [d][t] (final out).
// grid (Tt/64=16, Cc/128=4, Bb). smem 2x65536.
// ---------------------------------------------------------------------------
#define WB_STRIDE 65536
#define WB_SM (2*WB_STRIDE)
template<bool BF16OUT>
__global__ __launch_bounds__(256) void gemm_wB(
    const unsigned char* __restrict__ wh, const unsigned char* __restrict__ wl,
    const float* __restrict__ phi,
    const unsigned char* __restrict__ breh, const unsigned char* __restrict__ brel,
    const unsigned char* __restrict__ bimh, const unsigned char* __restrict__ biml,
    unsigned char* __restrict__ ovreh, unsigned char* __restrict__ ovrel,
    unsigned char* __restrict__ ovimh, unsigned char* __restrict__ oviml,
    float* __restrict__ fre, float* __restrict__ fim)
{
    extern __shared__ char sm[];
    __shared__ float s_cs[128], s_sn[128];
    const uint32_t smb = s2u(sm);
    const int tid = threadIdx.x, wid = tid >> 5, lane = tid & 31;
    const int wm = wid & 3, wn = wid >> 2;
    const int b = blockIdx.z, m0 = blockIdx.y * 128, n0 = blockIdx.x * 64;

    if (tid < 128) {
        float s, c; sincosf(phi[m0 + tid], &s, &c);
        s_cs[tid] = c; s_sn[tid] = s;
    }

    const unsigned char* brh = breh + (size_t)b * ZB;
    const unsigned char* brl = brel + (size_t)b * ZB;
    const unsigned char* bih = bimh + (size_t)b * ZB;
    const unsigned char* bil = biml + (size_t)b * ZB;

    auto issue = [&](int ch, uint32_t bs) {
        size_t ao = ((size_t)(ch * 512 + m0)) << 7;
        size_t bo = ((size_t)(ch * 1024 + n0)) << 7;
        cpreg(bs + 0,     wh + ao, 16384, tid);
        cpreg(bs + 16384, wl + ao, 16384, tid);
        cpreg(bs + 32768, brh + bo, 8192, tid);
        cpreg(bs + 40960, brl + bo, 8192, tid);
        cpreg(bs + 49152, bih + bo, 8192, tid);
        cpreg(bs + 57344, bil + bo, 8192, tid);
    };

    float accR[2][4][4] = {}, accI[2][4][4] = {};
    issue(0, smb); cpa_commit();
    for (int ch = 0; ch < 8; ch++) {
        uint32_t base = smb + (ch & 1) * WB_STRIDE;
        if (ch + 1 < 8) { issue(ch + 1, smb + ((ch + 1) & 1) * WB_STRIDE); cpa_commit(); cpa_wait1(); }
        else cpa_wait0();
        __syncthreads();
        #pragma unroll
        for (int ks = 0; ks < 4; ks++) {
            uint32_t aH[2][4], aL[2][4];
            #pragma unroll
            for (int mi = 0; mi < 2; mi++) {
                ldsm4(aH[mi], a_addr(base + 0,     wm * 32 + mi * 16, ks, lane));
                ldsm4(aL[mi], a_addr(base + 16384, wm * 32 + mi * 16, ks, lane));
            }
            uint32_t rH[8], rL[8], iH[8], iL[8];
            ldsm4(rH + 0, b_addr(base + 32768, wn * 32,      ks, lane));
            ldsm4(rH + 4, b_addr(base + 32768, wn * 32 + 16, ks, lane));
            ldsm4(rL + 0, b_addr(base + 40960, wn * 32,      ks, lane));
            ldsm4(rL + 4, b_addr(base + 40960, wn * 32 + 16, ks, lane));
            ldsm4(iH + 0, b_addr(base + 49152, wn * 32,      ks, lane));
            ldsm4(iH + 4, b_addr(base + 49152, wn * 32 + 16, ks, lane));
            ldsm4(iL + 0, b_addr(base + 57344, wn * 32,      ks, lane));
            ldsm4(iL + 4, b_addr(base + 57344, wn * 32 + 16, ks, lane));
            #pragma unroll
            for (int mi = 0; mi < 2; mi++)
                #pragma unroll
                for (int nf = 0; nf < 4; nf++) {
                    mma_split(accR[mi][nf], aH[mi], aL[mi], rH + nf * 2, rL + nf * 2);
                    mma_split(accI[mi][nf], aH[mi], aL[mi], iH + nf * 2, iL + nf * 2);
                }
        }
        __syncthreads();
    }

    const int g = lane >> 2, cp = (lane & 3) * 2;
    #pragma unroll
    for (int mi = 0; mi < 2; mi++) {
        const int lr = wm * 32 + mi * 16 + g;
        const float c0 = s_cs[lr], s0 = s_sn[lr], c8 = s_cs[lr + 8], s8 = s_sn[lr + 8];
        const int r0 = m0 + lr;
        #pragma unroll
        for (int nf = 0; nf < 4; nf++) {
            const int c = wn * 32 + nf * 8 + cp;
            float* aR = accR[mi][nf];
            float* aI = accI[mi][nf];
            float xr0 = aR[0]*c0 - aI[0]*s0, xr1 = aR[1]*c0 - aI[1]*s0;
            float xi0 = aR[0]*s0 + aI[0]*c0, xi1 = aR[1]*s0 + aI[1]*c0;
            float yr0 = aR[2]*c8 - aI[2]*s8, yr1 = aR[3]*c8 - aI[3]*s8;
            float yi0 = aR[2]*s8 + aI[2]*c8, yi1 = aR[3]*s8 + aI[3]*c8;
            if (BF16OUT) {
                unsigned char* vrh = ovreh + (size_t)b * VB;
                unsigned char* vrl = ovrel + (size_t)b * VB;
                unsigned char* vih = ovimh + (size_t)b * VB;
                unsigned char* vil = oviml + (size_t)b * VB;
                st_pair(vrh, vrl, 512, n0 >> 6, r0, c, xr0, xr1);
                st_pair(vih, vil, 512, n0 >> 6, r0, c, xi0, xi1);
                st_pair(vrh, vrl, 512, n0 >> 6, r0 + 8, c, yr0, yr1);
                st_pair(vih, vil, 512, n0 >> 6, r0 + 8, c, yi0, yi1);
            } else {
                float* dre = fre + (size_t)b * Cc * Tt;
                float* dim = fim + (size_t)b * Cc * Tt;
                *(float2*)&dre[(size_t)r0 * Tt + n0 + c]       = make_float2(xr0, xr1);
                *(float2*)&dim[(size_t)r0 * Tt + n0 + c]       = make_float2(xi0, xi1);
                *(float2*)&dre[(size_t)(r0 + 8) * Tt + n0 + c] = make_float2(yr0, yr1);
                *(float2*)&dim[(size_t)(r0 + 8) * Tt + n0 + c] = make_float2(yi0, yi1);
            }
        }
    }
}

// ---------------------------------------------------------------------------
// gemm_scores: S[t,u] = (Q·Kᵀre + im)/8, causal. grid (16, 8, Bb). smem 2x98304.
// ---------------------------------------------------------------------------
#define SC_STRIDE 98304
#define SC_SM (2*SC_STRIDE)
__global__ __launch_bounds__(256) void gemm_scores()
{
    extern __shared__ char sm[];
    const uint32_t smb = s2u(sm);
    const int tid = threadIdx.x, wid = tid >> 5, lane = tid & 31;
    const int wm = wid & 3, wn = wid >> 2;
    const int b = blockIdx.z, m0 = blockIdx.y * 128, n0 = blockIdx.x * 64;
    float* arow = g_attn + (size_t)b * Tt * Tt;
    const float ni = __int_as_float(0xff800000);

    if (n0 >= m0 + 128) {
        float4 v = make_float4(ni, ni, ni, ni);
        for (int i = tid; i < 128 * 16; i += 256) {
            int r = i >> 4, c4 = (i & 15) << 2;
            *(float4*)&arow[(size_t)(m0 + r) * Tt + n0 + c4] = v;
        }
        return;
    }

    const unsigned char* qrh = g_qreh + (size_t)b * ZB;
    const unsigned char* qrl = g_qrel + (size_t)b * ZB;
    const unsigned char* qih = g_qimh + (size_t)b * ZB;
    const unsigned char* qil = g_qiml + (size_t)b * ZB;
    const unsigned char* krh = g_kreh + (size_t)b * ZB;
    const unsigned char* krl = g_krel + (size_t)b * ZB;
    const unsigned char* kih = g_kimh + (size_t)b * ZB;
    const unsigned char* kil = g_kiml + (size_t)b * ZB;

    auto issue = [&](int ch, uint32_t bs) {
        size_t ao = ((size_t)(ch * 1024 + m0)) << 7;
        size_t bo = ((size_t)(ch * 1024 + n0)) << 7;
        cpreg(bs + 0,     qrh + ao, 16384, tid);
        cpreg(bs + 16384, qrl + ao, 16384, tid);
        cpreg(bs + 32768, qih + ao, 16384, tid);
        cpreg(bs + 49152, qil + ao, 16384, tid);
        cpreg(bs + 65536, krh + bo, 8192, tid);
        cpreg(bs + 73728, krl + bo, 8192, tid);
        cpreg(bs + 81920, kih + bo, 8192, tid);
        cpreg(bs + 90112, kil + bo, 8192, tid);
    };

    float acc[2][4][4] = {};
    issue(0, smb); cpa_commit();
    for (int ch = 0; ch < 8; ch++) {
        uint32_t base = smb + (ch & 1) * SC_STRIDE;
        if (ch + 1 < 8) { issue(ch + 1, smb + ((ch + 1) & 1) * SC_STRIDE); cpa_commit(); cpa_wait1(); }
        else cpa_wait0();
        __syncthreads();
        #pragma unroll
        for (int ks = 0; ks < 4; ks++) {
            uint32_t qRH[2][4], qRL[2][4], qIH[2][4], qIL[2][4];
            #pragma unroll
            for (int mi = 0; mi < 2; mi++) {
                ldsm4(qRH[mi], a_addr(base + 0,     wm * 32 + mi * 16, ks, lane));
                ldsm4(qRL[mi], a_addr(base + 16384, wm * 32 + mi * 16, ks, lane));
                ldsm4(qIH[mi], a_addr(base + 32768, wm * 32 + mi * 16, ks, lane));
                ldsm4(qIL[mi], a_addr(base + 49152, wm * 32 + mi * 16, ks, lane));
            }
            uint32_t rH[8], rL[8], iH[8], iL[8];
            ldsm4(rH + 0, b_addr(base + 65536, wn * 32,      ks, lane));
            ldsm4(rH + 4, b_addr(base + 65536, wn * 32 + 16, ks, lane));
            ldsm4(rL + 0, b_addr(base + 73728, wn * 32,      ks, lane));
            ldsm4(rL + 4, b_addr(base + 73728, wn * 32 + 16, ks, lane));
            ldsm4(iH + 0, b_addr(base + 81920, wn * 32,      ks, lane));
            ldsm4(iH + 4, b_addr(base + 81920, wn * 32 + 16, ks, lane));
            ldsm4(iL + 0, b_addr(base + 90112, wn * 32,      ks, lane));
            ldsm4(iL + 4, b_addr(base + 90112, wn * 32 + 16, ks, lane));
            #pragma unroll
            for (int mi = 0; mi < 2; mi++)
                #pragma unroll
                for (int nf = 0; nf < 4; nf++) {
                    mma_split(acc[mi][nf], qRH[mi], qRL[mi], rH + nf * 2, rL + nf * 2);
                    mma_split(acc[mi][nf], qIH[mi], qIL[mi], iH + nf * 2, iL + nf * 2);
                }
        }
        __syncthreads();
    }

    const int g = lane >> 2, cp = (lane & 3) * 2;
    #pragma unroll
    for (int mi = 0; mi < 2; mi++) {
        const int r0 = m0 + wm * 32 + mi * 16 + g;
        #pragma unroll
        for (int nf = 0; nf < 4; nf++) {
            const int u = n0 + wn * 32 + nf * 8 + cp;
            float* a = acc[mi][nf];
            float2 v0, v1;
            v0.x = (u     > r0) ? ni : a[0] * 0.125f;
            v0.y = (u + 1 > r0) ? ni : a[1] * 0.125f;
            v1.x = (u     > r0 + 8) ? ni : a[2] * 0.125f;
            v1.y = (u + 1 > r0 + 8) ? ni : a[3] * 0.125f;
            *(float2*)&arow[(size_t)r0 * Tt + u]       = v0;
            *(float2*)&arow[(size_t)(r0 + 8) * Tt + u] = v1;
        }
    }
}

// ---------------------------------------------------------------------------
// softmax: fp32 scores -> bf16 hi/lo chunked attn. grid (Tt, Bb), block 256
// ---------------------------------------------------------------------------
__global__ __launch_bounds__(256) void softmax_kernel()
{
    const int t = blockIdx.x, b = blockIdx.y;
    const float* row = g_attn + ((size_t)b * Tt + t) * Tt;
    const int tid = threadIdx.x;
    float4 v = ((const float4*)row)[tid];
    float m = fmaxf(fmaxf(v.x, v.y), fmaxf(v.z, v.w));
    __shared__ float red[8];
    #pragma unroll
    for (int o = 16; o > 0; o >>= 1) m = fmaxf(m, __shfl_xor_sync(0xffffffffu, m, o));
    if ((tid & 31) == 0) red[tid >> 5] = m;
    __syncthreads();
    if (tid == 0) {
        float mm = red[0];
        #pragma unroll
        for (int i = 1; i < 8; i++) mm = fmaxf(mm, red[i]);
        red[0] = mm;
    }
    __syncthreads();
    m = red[0];
    __syncthreads();
    float e0 = expf(v.x - m), e1 = expf(v.y - m), e2 = expf(v.z - m), e3 = expf(v.w - m);
    float s = e0 + e1 + e2 + e3;
    #pragma unroll
    for (int o = 16; o > 0; o >>= 1) s += __shfl_xor_sync(0xffffffffu, s, o);
    if ((tid & 31) == 0) red[tid >> 5] = s;
    __syncthreads();
    if (tid == 0) {
        float ss = 0.f;
        #pragma unroll
        for (int i = 0; i < 8; i++) ss += red[i];
        red[0] = ss;
    }
    __syncthreads();
    const float inv = 1.0f / red[0];
    unsigned char* ah = g_ath + (size_t)b * AB;
    unsigned char* al = g_atl + (size_t)b * AB;
    const int u = tid * 4;
    st_pair(ah, al, 1024, u >> 6, t, u & 63, e0 * inv, e1 * inv);
    st_pair(ah, al, 1024, u >> 6, t, (u & 63) + 2, e2 * inv, e3 * inv);
}

// ---------------------------------------------------------------------------
// gemm_av: O[t,c] = attn·Vᵀ (dual B = v re/im). K bounded causally.
// grid (Cc/64=8, Tt/128=8, Bb). smem 2x65536.
// ---------------------------------------------------------------------------
__global__ __launch_bounds__(256) void gemm_av()
{
    extern __shared__ char sm[];
    const uint32_t smb = s2u(sm);
    const int tid = threadIdx.x, wid = tid >> 5, lane = tid & 31;
    const int wm = wid & 3, wn = wid >> 2;
    const int b = blockIdx.z, m0 = blockIdx.y * 128, n0 = blockIdx.x * 64;

    const unsigned char* ah = g_ath + (size_t)b * AB;
    const unsigned char* al = g_atl + (size_t)b * AB;
    const unsigned char* vrh = g_vreh + (size_t)b * VB;
    const unsigned char* vrl = g_vrel + (size_t)b * VB;
    const unsigned char* vih = g_vimh + (size_t)b * VB;
    const unsigned char* vil = g_viml + (size_t)b * VB;

    auto issue = [&](int ch, uint32_t bs) {
        size_t ao = ((size_t)(ch * 1024 + m0)) << 7;
        size_t bo = ((size_t)(ch * 512 + n0)) << 7;
        cpreg(bs + 0,     ah + ao, 16384, tid);
        cpreg(bs + 16384, al + ao, 16384, tid);
        cpreg(bs + 32768, vrh + bo, 8192, tid);
        cpreg(bs + 40960, vrl + bo, 8192, tid);
        cpreg(bs + 49152, vih + bo, 8192, tid);
        cpreg(bs + 57344, vil + bo, 8192, tid);
    };

    float accR[2][4][4] = {}, accI[2][4][4] = {};
    const int nch = m0 / 64 + 2;
    issue(0, smb); cpa_commit();
    for (int ch = 0; ch < nch; ch++) {
        uint32_t base = smb + (ch & 1) * WB_STRIDE;
        if (ch + 1 < nch) { issue(ch + 1, smb + ((ch + 1) & 1) * WB_STRIDE); cpa_commit(); cpa_wait1(); }
        else cpa_wait0();
        __syncthreads();
        #pragma unroll
        for (int ks = 0; ks < 4; ks++) {
            uint32_t aH[2][4], aL[2][4];
            #pragma unroll
            for (int mi = 0; mi < 2; mi++) {
                ldsm4(aH[mi], a_addr(base + 0,     wm * 32 + mi * 16, ks, lane));
                ldsm4(aL[mi], a_addr(base + 16384, wm * 32 + mi * 16, ks, lane));
            }
            uint32_t rH[8], rL[8], iH[8], iL[8];
            ldsm4(rH + 0, b_addr(base + 32768, wn * 32,      ks, lane));
            ldsm4(rH + 4, b_addr(base + 32768, wn * 32 + 16, ks, lane));
            ldsm4(rL + 0, b_addr(base + 40960, wn * 32,      ks, lane));
            ldsm4(rL + 4, b_addr(base + 40960, wn * 32 + 16, ks, lane));
            ldsm4(iH + 0, b_addr(base + 49152, wn * 32,      ks, lane));
            ldsm4(iH + 4, b_addr(base + 49152, wn * 32 + 16, ks, lane));
            ldsm4(iL + 0, b_addr(base + 57344, wn * 32,      ks, lane));
            ldsm4(iL + 4, b_addr(base + 57344, wn * 32 + 16, ks, lane));
            #pragma unroll
            for (int mi = 0; mi < 2; mi++)
                #pragma unroll
                for (int nf = 0; nf < 4; nf++) {
                    mma_split(accR[mi][nf], aH[mi], aL[mi], rH + nf * 2, rL + nf * 2);
                    mma_split(accI[mi][nf], aH[mi], aL[mi], iH + nf * 2, iL + nf * 2);
                }
        }
        __syncthreads();
    }

    unsigned char* orh = g_oreh + (size_t)b * ZB;
    unsigned char* orl = g_orel + (size_t)b * ZB;
    unsigned char* oih = g_oimh + (size_t)b * ZB;
    unsigned char* oil = g_oiml + (size_t)b * ZB;
    const int g = lane >> 2, cp = (lane & 3) * 2, och = n0 >> 6;
    #pragma unroll
    for (int mi = 0; mi < 2; mi++) {
        const int r0 = m0 + wm * 32 + mi * 16 + g;
        #pragma unroll
        for (int nf = 0; nf < 4; nf++) {
            const int c = wn * 32 + nf * 8 + cp;
            float* aR = accR[mi][nf];
            float* aI = accI[mi][nf];
            st_pair(orh, orl, 1024, och, r0, c, aR[0], aR[1]);
            st_pair(oih, oil, 1024, och, r0, c, aI[0], aI[1]);
            st_pair(orh, orl, 1024, och, r0 + 8, c, aR[2], aR[3]);
            st_pair(oih, oil, 1024, och, r0 + 8, c, aI[2], aI[3]);
        }
    }
}

// ---------------------------------------------------------------------------
extern "C" void kernel_launch(void* const* d_in, const int* in_sizes, int n_in,
                              void* d_out, int out_size)
{
    const float* z_re  = (const float*)d_in[0];
    const float* z_im  = (const float*)d_in[1];
    const float* Wq    = (const float*)d_in[2];
    const float* phi_q = (const float*)d_in[3];
    const float* Wk    = (const float*)d_in[4];
    const float* phi_k = (const float*)d_in[5];
    const float* Wv    = (const float*)d_in[6];
    const float* phi_v = (const float*)d_in[7];
    const float* Wo    = (const float*)d_in[8];
    const float* phi_o = (const float*)d_in[9];

    unsigned char *wh, *wl;
    unsigned char *qreh, *qrel, *qimh, *qiml, *kreh, *krel, *kimh, *kiml;
    unsigned char *vreh, *vrel, *vimh, *viml, *oreh, *orel, *oimh, *oiml;
    unsigned char *zreh, *zrel, *zimh, *ziml;
    cudaGetSymbolAddress((void**)&wh, g_wh);   cudaGetSymbolAddress((void**)&wl, g_wl);
    cudaGetSymbolAddress((void**)&qreh, g_qreh); cudaGetSymbolAddress((void**)&qrel, g_qrel);
    cudaGetSymbolAddress((void**)&qimh, g_qimh); cudaGetSymbolAddress((void**)&qiml, g_qiml);
    cudaGetSymbolAddress((void**)&kreh, g_kreh); cudaGetSymbolAddress((void**)&krel, g_krel);
    cudaGetSymbolAddress((void**)&kimh, g_kimh); cudaGetSymbolAddress((void**)&kiml, g_kiml);
    cudaGetSymbolAddress((void**)&vreh, g_vreh); cudaGetSymbolAddress((void**)&vrel, g_vrel);
    cudaGetSymbolAddress((void**)&vimh, g_vimh); cudaGetSymbolAddress((void**)&viml, g_viml);
    cudaGetSymbolAddress((void**)&oreh, g_oreh); cudaGetSymbolAddress((void**)&orel, g_orel);
    cudaGetSymbolAddress((void**)&oimh, g_oimh); cudaGetSymbolAddress((void**)&oiml, g_oiml);
    cudaGetSymbolAddress((void**)&zreh, g_zreh); cudaGetSymbolAddress((void**)&zrel, g_zrel);
    cudaGetSymbolAddress((void**)&zimh, g_zimh); cudaGetSymbolAddress((void**)&ziml, g_ziml);

    cudaFuncSetAttribute(gemm_qk,        cudaFuncAttributeMaxDynamicSharedMemorySize, QK_SM);
    cudaFuncSetAttribute(gemm_wB<true>,  cudaFuncAttributeMaxDynamicSharedMemorySize, WB_SM);
    cudaFuncSetAttribute(gemm_wB<false>, cudaFuncAttributeMaxDynamicSharedMemorySize, WB_SM);
    cudaFuncSetAttribute(gemm_scores,    cudaFuncAttributeMaxDynamicSharedMemorySize, SC_SM);
    cudaFuncSetAttribute(gemm_av,        cudaFuncAttributeMaxDynamicSharedMemorySize, WB_SM);

    float* out_re = (float*)d_out;
    float* out_im = out_re + (size_t)BCT;

    dim3 blk(256);
    prep_z<<<dim3(32, 8, Bb), blk>>>(z_re, z_im);
    prep_w<<<dim3(8, 4), blk>>>(Wq, Wk, Wv, Wo);
    gemm_qk<<<dim3(8, 8, Bb), blk, QK_SM>>>(wh + 0*WBY, wl + 0*WBY, phi_q, qreh, qrel, qimh, qiml);
    gemm_qk<<<dim3(8, 8, Bb), blk, QK_SM>>>(wh + 1*WBY, wl + 1*WBY, phi_k, kreh, krel, kimh, kiml);
    gemm_wB<true><<<dim3(16, 4, Bb), blk, WB_SM>>>(wh + 2*WBY, wl + 2*WBY, phi_v,
        zreh, zrel, zimh, ziml, vreh, vrel, vimh, viml, nullptr, nullptr);
    gemm_scores<<<dim3(16, 8, Bb), blk, SC_SM>>>();
    softmax_kernel<<<dim3(Tt, Bb), blk>>>();
    gemm_av<<<dim3(8, 8, Bb), blk, WB_SM>>>();
    gemm_wB<false><<<dim3(16, 4, Bb), blk, WB_SM>>>(wh + 3*WBY, wl + 3*WBY, phi_o,
        oreh, orel, oimh, oiml, nullptr, nullptr, nullptr, nullptr, out_re, out_im);
}

// round 6
// speedup vs baseline: 2.4776x; 1.0511x over previous
#include <cuda_runtime.h>
#include <cuda_bf16.h>
#include <cstdint>
#include <math.h>

#define Bb 8
#define Cc 512
#define Tt 1024
#define BCT (Bb*Cc*Tt)
#define BTT (Bb*Tt*Tt)

// chunked bf16 tensor layout: [ch][R rows][128B], swizzled per-row:
// byte(col,row) = (col*2) ^ ((row&7)<<4)
#define ZB (8*1024*128)
#define VB (16*512*128)
#define AB (16*1024*128)
#define WBY (8*512*128)

__device__ __align__(16) unsigned char g_zreh[Bb*ZB], g_zrel[Bb*ZB], g_zimh[Bb*ZB], g_ziml[Bb*ZB];
__device__ __align__(16) unsigned char g_qreh[Bb*ZB], g_qrel[Bb*ZB], g_qimh[Bb*ZB], g_qiml[Bb*ZB];
__device__ __align__(16) unsigned char g_kreh[Bb*ZB], g_krel[Bb*ZB], g_kimh[Bb*ZB], g_kiml[Bb*ZB];
__device__ __align__(16) unsigned char g_vreh[Bb*VB], g_vrel[Bb*VB], g_vimh[Bb*VB], g_viml[Bb*VB];
__device__ __align__(16) unsigned char g_ath[Bb*AB],  g_atl[Bb*AB];
__device__ __align__(16) unsigned char g_oreh[Bb*ZB], g_orel[Bb*ZB], g_oimh[Bb*ZB], g_oiml[Bb*ZB];
__device__ __align__(16) unsigned char g_wh[4*WBY],   g_wl[4*WBY];
__device__ float g_attn[BTT];

#define SW128(o) ((o) ^ (((o) >> 3) & 0x70))
#define NT 512

__device__ __forceinline__ uint32_t s2u(const void* p) {
    uint32_t a;
    asm("{ .reg .u64 t; cvta.to.shared.u64 t, %1; cvt.u32.u64 %0, t; }" : "=r"(a) : "l"(p));
    return a;
}
__device__ __forceinline__ uint32_t pk2(__nv_bfloat16 a, __nv_bfloat16 b) {
    return ((uint32_t)__bfloat16_as_ushort(b) << 16) | (uint32_t)__bfloat16_as_ushort(a);
}
__device__ __forceinline__ void st_pair(unsigned char* bh, unsigned char* bl,
                                        int R, int ch, int row, int col, float v0, float v1) {
    size_t off = (((size_t)ch * R + row) << 7) + (uint32_t)((col * 2) ^ ((row & 7) << 4));
    __nv_bfloat16 h0 = __float2bfloat16(v0), h1 = __float2bfloat16(v1);
    *(uint32_t*)(bh + off) = pk2(h0, h1);
    __nv_bfloat16 l0 = __float2bfloat16(v0 - __bfloat162float(h0));
    __nv_bfloat16 l1 = __float2bfloat16(v1 - __bfloat162float(h1));
    *(uint32_t*)(bl + off) = pk2(l0, l1);
}
__device__ __forceinline__ void cpa16(uint32_t s, const void* g) {
    asm volatile("cp.async.cg.shared.global [%0], [%1], 16;" :: "r"(s), "l"(g) : "memory");
}
__device__ __forceinline__ void cpa_commit() { asm volatile("cp.async.commit_group;" ::: "memory"); }
__device__ __forceinline__ void cpa_wait1()  { asm volatile("cp.async.wait_group 1;" ::: "memory"); }
__device__ __forceinline__ void cpa_wait0()  { asm volatile("cp.async.wait_group 0;" ::: "memory"); }
__device__ __forceinline__ void cpreg(uint32_t s, const unsigned char* g, int nbytes, int tid) {
    for (int o = tid * 16; o < nbytes; o += NT * 16) cpa16(s + o, g + o);
}
__device__ __forceinline__ void ldsm4(uint32_t* r, uint32_t addr) {
    asm volatile("ldmatrix.sync.aligned.m8n8.x4.shared.b16 {%0,%1,%2,%3}, [%4];"
                 : "=r"(r[0]), "=r"(r[1]), "=r"(r[2]), "=r"(r[3]) : "r"(addr));
}
__device__ __forceinline__ void mma16816(float* d, const uint32_t* a, const uint32_t* b) {
    asm volatile(
        "mma.sync.aligned.m16n8k16.row.col.f32.bf16.bf16.f32 "
        "{%0,%1,%2,%3}, {%4,%5,%6,%7}, {%8,%9}, {%0,%1,%2,%3};"
        : "+f"(d[0]), "+f"(d[1]), "+f"(d[2]), "+f"(d[3])
        : "r"(a[0]), "r"(a[1]), "r"(a[2]), "r"(a[3]), "r"(b[0]), "r"(b[1]));
}
__device__ __forceinline__ void mma_split(float* d, const uint32_t* aH, const uint32_t* aL,
                                          const uint32_t* bH, const uint32_t* bL) {
    mma16816(d, aH, bH);
    mma16816(d, aH, bL);
    mma16816(d, aL, bH);
}
__device__ __forceinline__ uint32_t a_addr(uint32_t base, int mbase, int ks, int lane) {
    int row = mbase + (lane & 15);
    int byt = ks * 32 + ((lane >> 4) << 4);
    return base + SW128((uint32_t)(row * 128 + byt));
}
__device__ __forceinline__ uint32_t b_addr(uint32_t base, int nbase, int ks, int lane) {
    int row = nbase + ((lane >> 4) << 3) + (lane & 7);
    int byt = ks * 32 + (((lane >> 3) & 1) << 4);
    return base + SW128((uint32_t)(row * 128 + byt));
}

// ---------------------------------------------------------------------------
// prep_z: fp32 z[b][c][t] -> chunked bf16 hi/lo [b][c/64][t][128B] (transpose)
// ---------------------------------------------------------------------------
__global__ __launch_bounds__(256) void prep_z(
    const float* __restrict__ zre, const float* __restrict__ zim)
{
    __shared__ float sre[64][33], sim[64][33];
    const int b = blockIdx.z, t0 = blockIdx.x * 32, c0 = blockIdx.y * 64;
    const int tid = threadIdx.x;
    const float* pre = zre + (size_t)b * Cc * Tt;
    const float* pim = zim + (size_t)b * Cc * Tt;
    for (int i = tid; i < 2048; i += 256) {
        int cl = i >> 5, tl = i & 31;
        sre[cl][tl] = pre[(size_t)(c0 + cl) * Tt + t0 + tl];
        sim[cl][tl] = pim[(size_t)(c0 + cl) * Tt + t0 + tl];
    }
    __syncthreads();
    unsigned char* zrh = g_zreh + (size_t)b * ZB;
    unsigned char* zrl = g_zrel + (size_t)b * ZB;
    unsigned char* zih = g_zimh + (size_t)b * ZB;
    unsigned char* zil = g_ziml + (size_t)b * ZB;
    const int ch = c0 >> 6;
    for (int i = tid; i < 1024; i += 256) {
        int tl = i >> 5, p = i & 31;
        int t = t0 + tl, col = p * 2;
        st_pair(zrh, zrl, 1024, ch, t, col, sre[col][tl], sre[col + 1][tl]);
        st_pair(zih, zil, 1024, ch, t, col, sim[col][tl], sim[col + 1][tl]);
    }
}

// ---------------------------------------------------------------------------
__global__ __launch_bounds__(256) void prep_w(
    const float* __restrict__ W0, const float* __restrict__ W1,
    const float* __restrict__ W2, const float* __restrict__ W3)
{
    const int d0 = blockIdx.x * 64, wi = blockIdx.y, tid = threadIdx.x;
    const float* W = (wi == 0) ? W0 : (wi == 1) ? W1 : (wi == 2) ? W2 : W3;
    unsigned char* oh = g_wh + (size_t)wi * WBY;
    unsigned char* ol = g_wl + (size_t)wi * WBY;
    for (int i = tid; i < 8192; i += 256) {
        int dl = i >> 7, q = i & 127;
        int c = q * 4, d = d0 + dl;
        float4 v = *(const float4*)&W[(size_t)d * Cc + c];
        st_pair(oh, ol, 512, c >> 6, d, c & 63, v.x, v.y);
        st_pair(oh, ol, 512, c >> 6, d, (c & 63) + 2, v.z, v.w);
    }
}

// ---------------------------------------------------------------------------
// gemm_qk: D[t,d] = rot_col( zT·W ). 512 thr, warp grid 4m x 4n (32x16 tiles).
// grid (Cc/64=8, Tt/128=8, Bb). smem 2x81920.
// ---------------------------------------------------------------------------
#define QK_STRIDE 81920
#define QK_SM (2*QK_STRIDE)
__global__ __launch_bounds__(NT) void gemm_qk(
    const unsigned char* __restrict__ wh, const unsigned char* __restrict__ wl,
    const float* __restrict__ phi,
    unsigned char* __restrict__ dreh, unsigned char* __restrict__ drel,
    unsigned char* __restrict__ dimh, unsigned char* __restrict__ diml)
{
    extern __shared__ char sm[];
    __shared__ float s_cs[64], s_sn[64];
    const uint32_t smb = s2u(sm);
    const int tid = threadIdx.x, wid = tid >> 5, lane = tid & 31;
    const int wm = wid & 3, wn = wid >> 2;
    const int b = blockIdx.z, m0 = blockIdx.y * 128, n0 = blockIdx.x * 64;

    if (tid < 64) {
        float s, c; sincosf(phi[n0 + tid], &s, &c);
        s_cs[tid] = c; s_sn[tid] = s;
    }

    const unsigned char* zrh = g_zreh + (size_t)b * ZB;
    const unsigned char* zrl = g_zrel + (size_t)b * ZB;
    const unsigned char* zih = g_zimh + (size_t)b * ZB;
    const unsigned char* zil = g_ziml + (size_t)b * ZB;

    auto issue = [&](int ch, uint32_t bs) {
        size_t ao = ((size_t)(ch * 1024 + m0)) << 7;
        size_t bo = ((size_t)(ch * 512 + n0)) << 7;
        cpreg(bs + 0,     zrh + ao, 16384, tid);
        cpreg(bs + 16384, zrl + ao, 16384, tid);
        cpreg(bs + 32768, zih + ao, 16384, tid);
        cpreg(bs + 49152, zil + ao, 16384, tid);
        cpreg(bs + 65536, wh + bo, 8192, tid);
        cpreg(bs + 73728, wl + bo, 8192, tid);
    };

    float accR[2][2][4] = {}, accI[2][2][4] = {};
    issue(0, smb); cpa_commit();
    for (int ch = 0; ch < 8; ch++) {
        uint32_t base = smb + (ch & 1) * QK_STRIDE;
        if (ch + 1 < 8) { issue(ch + 1, smb + ((ch + 1) & 1) * QK_STRIDE); cpa_commit(); cpa_wait1(); }
        else cpa_wait0();
        __syncthreads();
        #pragma unroll
        for (int ks = 0; ks < 4; ks++) {
            uint32_t arH[2][4], arL[2][4], aiH[2][4], aiL[2][4];
            #pragma unroll
            for (int mi = 0; mi < 2; mi++) {
                ldsm4(arH[mi], a_addr(base + 0,     wm * 32 + mi * 16, ks, lane));
                ldsm4(arL[mi], a_addr(base + 16384, wm * 32 + mi * 16, ks, lane));
                ldsm4(aiH[mi], a_addr(base + 32768, wm * 32 + mi * 16, ks, lane));
                ldsm4(aiL[mi], a_addr(base + 49152, wm * 32 + mi * 16, ks, lane));
            }
            uint32_t bH[4], bL[4];
            ldsm4(bH, b_addr(base + 65536, wn * 16, ks, lane));
            ldsm4(bL, b_addr(base + 73728, wn * 16, ks, lane));
            #pragma unroll
            for (int mi = 0; mi < 2; mi++)
                #pragma unroll
                for (int nf = 0; nf < 2; nf++) {
                    mma_split(accR[mi][nf], arH[mi], arL[mi], bH + nf * 2, bL + nf * 2);
                    mma_split(accI[mi][nf], aiH[mi], aiL[mi], bH + nf * 2, bL + nf * 2);
                }
        }
        __syncthreads();
    }

    unsigned char* qrh = dreh + (size_t)b * ZB;
    unsigned char* qrl = drel + (size_t)b * ZB;
    unsigned char* qih = dimh + (size_t)b * ZB;
    unsigned char* qil = diml + (size_t)b * ZB;
    const int g = lane >> 2, cp = (lane & 3) * 2, och = n0 >> 6;
    #pragma unroll
    for (int mi = 0; mi < 2; mi++) {
        const int r0 = m0 + wm * 32 + mi * 16 + g;
        #pragma unroll
        for (int nf = 0; nf < 2; nf++) {
            const int c = wn * 16 + nf * 8 + cp;
            float c0 = s_cs[c], s0 = s_sn[c], c1 = s_cs[c + 1], s1 = s_sn[c + 1];
            float* aR = accR[mi][nf];
            float* aI = accI[mi][nf];
            st_pair(qrh, qrl, 1024, och, r0, c, aR[0]*c0 - aI[0]*s0, aR[1]*c1 - aI[1]*s1);
            st_pair(qih, qil, 1024, och, r0, c, aR[0]*s0 + aI[0]*c0, aR[1]*s1 + aI[1]*c1);
            st_pair(qrh, qrl, 1024, och, r0 + 8, c, aR[2]*c0 - aI[2]*s0, aR[3]*c1 - aI[3]*s1);
            st_pair(qih, qil, 1024, och, r0 + 8, c, aR[2]*s0 + aI[2]*c0, aR[3]*s1 + aI[3]*c1);
        }
    }
}

// ---------------------------------------------------------------------------
// gemm_wB: D[d,n] = rot_row( W·Bᵀ ). grid (Tt/64=16, Cc/128=4, Bb). smem 2x65536.
// ---------------------------------------------------------------------------
#define WB_STRIDE 65536
#define WB_SM (2*WB_STRIDE)
template<bool BF16OUT>
__global__ __launch_bounds__(NT) void gemm_wB(
    const unsigned char* __restrict__ wh, const unsigned char* __restrict__ wl,
    const float* __restrict__ phi,
    const unsigned char* __restrict__ breh, const unsigned char* __restrict__ brel,
    const unsigned char* __restrict__ bimh, const unsigned char* __restrict__ biml,
    unsigned char* __restrict__ ovreh, unsigned char* __restrict__ ovrel,
    unsigned char* __restrict__ ovimh, unsigned char* __restrict__ oviml,
    float* __restrict__ fre, float* __restrict__ fim)
{
    extern __shared__ char sm[];
    __shared__ float s_cs[128], s_sn[128];
    const uint32_t smb = s2u(sm);
    const int tid = threadIdx.x, wid = tid >> 5, lane = tid & 31;
    const int wm = wid & 3, wn = wid >> 2;
    const int b = blockIdx.z, m0 = blockIdx.y * 128, n0 = blockIdx.x * 64;

    if (tid < 128) {
        float s, c; sincosf(phi[m0 + tid], &s, &c);
        s_cs[tid] = c; s_sn[tid] = s;
    }

    const unsigned char* brh = breh + (size_t)b * ZB;
    const unsigned char* brl = brel + (size_t)b * ZB;
    const unsigned char* bih = bimh + (size_t)b * ZB;
    const unsigned char* bil = biml + (size_t)b * ZB;

    auto issue = [&](int ch, uint32_t bs) {
        size_t ao = ((size_t)(ch * 512 + m0)) << 7;
        size_t bo = ((size_t)(ch * 1024 + n0)) << 7;
        cpreg(bs + 0,     wh + ao, 16384, tid);
        cpreg(bs + 16384, wl + ao, 16384, tid);
        cpreg(bs + 32768, brh + bo, 8192, tid);
        cpreg(bs + 40960, brl + bo, 8192, tid);
        cpreg(bs + 49152, bih + bo, 8192, tid);
        cpreg(bs + 57344, bil + bo, 8192, tid);
    };

    float accR[2][2][4] = {}, accI[2][2][4] = {};
    issue(0, smb); cpa_commit();
    for (int ch = 0; ch < 8; ch++) {
        uint32_t base = smb + (ch & 1) * WB_STRIDE;
        if (ch + 1 < 8) { issue(ch + 1, smb + ((ch + 1) & 1) * WB_STRIDE); cpa_commit(); cpa_wait1(); }
        else cpa_wait0();
        __syncthreads();
        #pragma unroll
        for (int ks = 0; ks < 4; ks++) {
            uint32_t aH[2][4], aL[2][4];
            #pragma unroll
            for (int mi = 0; mi < 2; mi++) {
                ldsm4(aH[mi], a_addr(base + 0,     wm * 32 + mi * 16, ks, lane));
                ldsm4(aL[mi], a_addr(base + 16384, wm * 32 + mi * 16, ks, lane));
            }
            uint32_t rH[4], rL[4], iH[4], iL[4];
            ldsm4(rH, b_addr(base + 32768, wn * 16, ks, lane));
            ldsm4(rL, b_addr(base + 40960, wn * 16, ks, lane));
            ldsm4(iH, b_addr(base + 49152, wn * 16, ks, lane));
            ldsm4(iL, b_addr(base + 57344, wn * 16, ks, lane));
            #pragma unroll
            for (int mi = 0; mi < 2; mi++)
                #pragma unroll
                for (int nf = 0; nf < 2; nf++) {
                    mma_split(accR[mi][nf], aH[mi], aL[mi], rH + nf * 2, rL + nf * 2);
                    mma_split(accI[mi][nf], aH[mi], aL[mi], iH + nf * 2, iL + nf * 2);
                }
        }
        __syncthreads();
    }

    const int g = lane >> 2, cp = (lane & 3) * 2;
    #pragma unroll
    for (int mi = 0; mi < 2; mi++) {
        const int lr = wm * 32 + mi * 16 + g;
        const float c0 = s_cs[lr], s0 = s_sn[lr], c8 = s_cs[lr + 8], s8 = s_sn[lr + 8];
        const int r0 = m0 + lr;
        #pragma unroll
        for (int nf = 0; nf < 2; nf++) {
            const int c = wn * 16 + nf * 8 + cp;
            float* aR = accR[mi][nf];
            float* aI = accI[mi][nf];
            float xr0 = aR[0]*c0 - aI[0]*s0, xr1 = aR[1]*c0 - aI[1]*s0;
            float xi0 = aR[0]*s0 + aI[0]*c0, xi1 = aR[1]*s0 + aI[1]*c0;
            float yr0 = aR[2]*c8 - aI[2]*s8, yr1 = aR[3]*c8 - aI[3]*s8;
            float yi0 = aR[2]*s8 + aI[2]*c8, yi1 = aR[3]*s8 + aI[3]*c8;
            if (BF16OUT) {
                unsigned char* vrh = ovreh + (size_t)b * VB;
                unsigned char* vrl = ovrel + (size_t)b * VB;
                unsigned char* vih = ovimh + (size_t)b * VB;
                unsigned char* vil = oviml + (size_t)b * VB;
                st_pair(vrh, vrl, 512, n0 >> 6, r0, c, xr0, xr1);
                st_pair(vih, vil, 512, n0 >> 6, r0, c, xi0, xi1);
                st_pair(vrh, vrl, 512, n0 >> 6, r0 + 8, c, yr0, yr1);
                st_pair(vih, vil, 512, n0 >> 6, r0 + 8, c, yi0, yi1);
            } else {
                float* dre = fre + (size_t)b * Cc * Tt;
                float* dim = fim + (size_t)b * Cc * Tt;
                *(float2*)&dre[(size_t)r0 * Tt + n0 + c]       = make_float2(xr0, xr1);
                *(float2*)&dim[(size_t)r0 * Tt + n0 + c]       = make_float2(xi0, xi1);
                *(float2*)&dre[(size_t)(r0 + 8) * Tt + n0 + c] = make_float2(yr0, yr1);
                *(float2*)&dim[(size_t)(r0 + 8) * Tt + n0 + c] = make_float2(yi0, yi1);
            }
        }
    }
}

// ---------------------------------------------------------------------------
// gemm_scores: S[t,u] = (Q·Kᵀre + im)/8, causal. grid (16, 8, Bb). smem 2x98304.
// ---------------------------------------------------------------------------
#define SC_STRIDE 98304
#define SC_SM (2*SC_STRIDE)
__global__ __launch_bounds__(NT) void gemm_scores()
{
    extern __shared__ char sm[];
    const uint32_t smb = s2u(sm);
    const int tid = threadIdx.x, wid = tid >> 5, lane = tid & 31;
    const int wm = wid & 3, wn = wid >> 2;
    const int b = blockIdx.z, m0 = blockIdx.y * 128, n0 = blockIdx.x * 64;
    float* arow = g_attn + (size_t)b * Tt * Tt;
    const float ni = __int_as_float(0xff800000);

    if (n0 >= m0 + 128) {
        float4 v = make_float4(ni, ni, ni, ni);
        for (int i = tid; i < 128 * 16; i += NT) {
            int r = i >> 4, c4 = (i & 15) << 2;
            *(float4*)&arow[(size_t)(m0 + r) * Tt + n0 + c4] = v;
        }
        return;
    }

    const unsigned char* qrh = g_qreh + (size_t)b * ZB;
    const unsigned char* qrl = g_qrel + (size_t)b * ZB;
    const unsigned char* qih = g_qimh + (size_t)b * ZB;
    const unsigned char* qil = g_qiml + (size_t)b * ZB;
    const unsigned char* krh = g_kreh + (size_t)b * ZB;
    const unsigned char* krl = g_krel + (size_t)b * ZB;
    const unsigned char* kih = g_kimh + (size_t)b * ZB;
    const unsigned char* kil = g_kiml + (size_t)b * ZB;

    auto issue = [&](int ch, uint32_t bs) {
        size_t ao = ((size_t)(ch * 1024 + m0)) << 7;
        size_t bo = ((size_t)(ch * 1024 + n0)) << 7;
        cpreg(bs + 0,     qrh + ao, 16384, tid);
        cpreg(bs + 16384, qrl + ao, 16384, tid);
        cpreg(bs + 32768, qih + ao, 16384, tid);
        cpreg(bs + 49152, qil + ao, 16384, tid);
        cpreg(bs + 65536, krh + bo, 8192, tid);
        cpreg(bs + 73728, krl + bo, 8192, tid);
        cpreg(bs + 81920, kih + bo, 8192, tid);
        cpreg(bs + 90112, kil + bo, 8192, tid);
    };

    float acc[2][2][4] = {};
    issue(0, smb); cpa_commit();
    for (int ch = 0; ch < 8; ch++) {
        uint32_t base = smb + (ch & 1) * SC_STRIDE;
        if (ch + 1 < 8) { issue(ch + 1, smb + ((ch + 1) & 1) * SC_STRIDE); cpa_commit(); cpa_wait1(); }
        else cpa_wait0();
        __syncthreads();
        #pragma unroll
        for (int ks = 0; ks < 4; ks++) {
            uint32_t qRH[2][4], qRL[2][4], qIH[2][4], qIL[2][4];
            #pragma unroll
            for (int mi = 0; mi < 2; mi++) {
                ldsm4(qRH[mi], a_addr(base + 0,     wm * 32 + mi * 16, ks, lane));
                ldsm4(qRL[mi], a_addr(base + 16384, wm * 32 + mi * 16, ks, lane));
                ldsm4(qIH[mi], a_addr(base + 32768, wm * 32 + mi * 16, ks, lane));
                ldsm4(qIL[mi], a_addr(base + 49152, wm * 32 + mi * 16, ks, lane));
            }
            uint32_t rH[4], rL[4], iH[4], iL[4];
            ldsm4(rH, b_addr(base + 65536, wn * 16, ks, lane));
            ldsm4(rL, b_addr(base + 73728, wn * 16, ks, lane));
            ldsm4(iH, b_addr(base + 81920, wn * 16, ks, lane));
            ldsm4(iL, b_addr(base + 90112, wn * 16, ks, lane));
            #pragma unroll
            for (int mi = 0; mi < 2; mi++)
                #pragma unroll
                for (int nf = 0; nf < 2; nf++) {
                    mma_split(acc[mi][nf], qRH[mi], qRL[mi], rH + nf * 2, rL + nf * 2);
                    mma_split(acc[mi][nf], qIH[mi], qIL[mi], iH + nf * 2, iL + nf * 2);
                }
        }
        __syncthreads();
    }

    const int g = lane >> 2, cp = (lane & 3) * 2;
    #pragma unroll
    for (int mi = 0; mi < 2; mi++) {
        const int r0 = m0 + wm * 32 + mi * 16 + g;
        #pragma unroll
        for (int nf = 0; nf < 2; nf++) {
            const int u = n0 + wn * 16 + nf * 8 + cp;
            float* a = acc[mi][nf];
            float2 v0, v1;
            v0.x = (u     > r0) ? ni : a[0] * 0.125f;
            v0.y = (u + 1 > r0) ? ni : a[1] * 0.125f;
            v1.x = (u     > r0 + 8) ? ni : a[2] * 0.125f;
            v1.y = (u + 1 > r0 + 8) ? ni : a[3] * 0.125f;
            *(float2*)&arow[(size_t)r0 * Tt + u]       = v0;
            *(float2*)&arow[(size_t)(r0 + 8) * Tt + u] = v1;
        }
    }
}

// ---------------------------------------------------------------------------
__global__ __launch_bounds__(256) void softmax_kernel()
{
    const int t = blockIdx.x, b = blockIdx.y;
    const float* row = g_attn + ((size_t)b * Tt + t) * Tt;
    const int tid = threadIdx.x;
    float4 v = ((const float4*)row)[tid];
    float m = fmaxf(fmaxf(v.x, v.y), fmaxf(v.z, v.w));
    __shared__ float red[8];
    #pragma unroll
    for (int o = 16; o > 0; o >>= 1) m = fmaxf(m, __shfl_xor_sync(0xffffffffu, m, o));
    if ((tid & 31) == 0) red[tid >> 5] = m;
    __syncthreads();
    if (tid == 0) {
        float mm = red[0];
        #pragma unroll
        for (int i = 1; i < 8; i++) mm = fmaxf(mm, red[i]);
        red[0] = mm;
    }
    __syncthreads();
    m = red[0];
    __syncthreads();
    float e0 = expf(v.x - m), e1 = expf(v.y - m), e2 = expf(v.z - m), e3 = expf(v.w - m);
    float s = e0 + e1 + e2 + e3;
    #pragma unroll
    for (int o = 16; o > 0; o >>= 1) s += __shfl_xor_sync(0xffffffffu, s, o);
    if ((tid & 31) == 0) red[tid >> 5] = s;
    __syncthreads();
    if (tid == 0) {
        float ss = 0.f;
        #pragma unroll
        for (int i = 0; i < 8; i++) ss += red[i];
        red[0] = ss;
    }
    __syncthreads();
    const float inv = 1.0f / red[0];
    unsigned char* ah = g_ath + (size_t)b * AB;
    unsigned char* al = g_atl + (size_t)b * AB;
    const int u = tid * 4;
    st_pair(ah, al, 1024, u >> 6, t, u & 63, e0 * inv, e1 * inv);
    st_pair(ah, al, 1024, u >> 6, t, (u & 63) + 2, e2 * inv, e3 * inv);
}

// ---------------------------------------------------------------------------
// gemm_av: O[t,c] = attn·Vᵀ. K bounded causally. grid (8, 8, Bb). smem 2x65536.
// ---------------------------------------------------------------------------
__global__ __launch_bounds__(NT) void gemm_av()
{
    extern __shared__ char sm[];
    const uint32_t smb = s2u(sm);
    const int tid = threadIdx.x, wid = tid >> 5, lane = tid & 31;
    const int wm = wid & 3, wn = wid >> 2;
    const int b = blockIdx.z, m0 = blockIdx.y * 128, n0 = blockIdx.x * 64;

    const unsigned char* ah = g_ath + (size_t)b * AB;
    const unsigned char* al = g_atl + (size_t)b * AB;
    const unsigned char* vrh = g_vreh + (size_t)b * VB;
    const unsigned char* vrl = g_vrel + (size_t)b * VB;
    const unsigned char* vih = g_vimh + (size_t)b * VB;
    const unsigned char* vil = g_viml + (size_t)b * VB;

    auto issue = [&](int ch, uint32_t bs) {
        size_t ao = ((size_t)(ch * 1024 + m0)) << 7;
        size_t bo = ((size_t)(ch * 512 + n0)) << 7;
        cpreg(bs + 0,     ah + ao, 16384, tid);
        cpreg(bs + 16384, al + ao, 16384, tid);
        cpreg(bs + 32768, vrh + bo, 8192, tid);
        cpreg(bs + 40960, vrl + bo, 8192, tid);
        cpreg(bs + 49152, vih + bo, 8192, tid);
        cpreg(bs + 57344, vil + bo, 8192, tid);
    };

    float accR[2][2][4] = {}, accI[2][2][4] = {};
    const int nch = m0 / 64 + 2;
    issue(0, smb); cpa_commit();
    for (int ch = 0; ch < nch; ch++) {
        uint32_t base = smb + (ch & 1) * WB_STRIDE;
        if (ch + 1 < nch) { issue(ch + 1, smb + ((ch + 1) & 1) * WB_STRIDE); cpa_commit(); cpa_wait1(); }
        else cpa_wait0();
        __syncthreads();
        #pragma unroll
        for (int ks = 0; ks < 4; ks++) {
            uint32_t aH[2][4], aL[2][4];
            #pragma unroll
            for (int mi = 0; mi < 2; mi++) {
                ldsm4(aH[mi], a_addr(base + 0,     wm * 32 + mi * 16, ks, lane));
                ldsm4(aL[mi], a_addr(base + 16384, wm * 32 + mi * 16, ks, lane));
            }
            uint32_t rH[4], rL[4], iH[4], iL[4];
            ldsm4(rH, b_addr(base + 32768, wn * 16, ks, lane));
            ldsm4(rL, b_addr(base + 40960, wn * 16, ks, lane));
            ldsm4(iH, b_addr(base + 49152, wn * 16, ks, lane));
            ldsm4(iL, b_addr(base + 57344, wn * 16, ks, lane));
            #pragma unroll
            for (int mi = 0; mi < 2; mi++)
                #pragma unroll
                for (int nf = 0; nf < 2; nf++) {
                    mma_split(accR[mi][nf], aH[mi], aL[mi], rH + nf * 2, rL + nf * 2);
                    mma_split(accI[mi][nf], aH[mi], aL[mi], iH + nf * 2, iL + nf * 2);
                }
        }
        __syncthreads();
    }

    unsigned char* orh = g_oreh + (size_t)b * ZB;
    unsigned char* orl = g_orel + (size_t)b * ZB;
    unsigned char* oih = g_oimh + (size_t)b * ZB;
    unsigned char* oil = g_oiml + (size_t)b * ZB;
    const int g = lane >> 2, cp = (lane & 3) * 2, och = n0 >> 6;
    #pragma unroll
    for (int mi = 0; mi < 2; mi++) {
        const int r0 = m0 + wm * 32 + mi * 16 + g;
        #pragma unroll
        for (int nf = 0; nf < 2; nf++) {
            const int c = wn * 16 + nf * 8 + cp;
            float* aR = accR[mi][nf];
            float* aI = accI[mi][nf];
            st_pair(orh, orl, 1024, och, r0, c, aR[0], aR[1]);
            st_pair(oih, oil, 1024, och, r0, c, aI[0], aI[1]);
            st_pair(orh, orl, 1024, och, r0 + 8, c, aR[2], aR[3]);
            st_pair(oih, oil, 1024, och, r0 + 8, c, aI[2], aI[3]);
        }
    }
}

// ---------------------------------------------------------------------------
extern "C" void kernel_launch(void* const* d_in, const int* in_sizes, int n_in,
                              void* d_out, int out_size)
{
    const float* z_re  = (const float*)d_in[0];
    const float* z_im  = (const float*)d_in[1];
    const float* Wq    = (const float*)d_in[2];
    const float* phi_q = (const float*)d_in[3];
    const float* Wk    = (const float*)d_in[4];
    const float* phi_k = (const float*)d_in[5];
    const float* Wv    = (const float*)d_in[6];
    const float* phi_v = (const float*)d_in[7];
    const float* Wo    = (const float*)d_in[8];
    const float* phi_o = (const float*)d_in[9];

    unsigned char *wh, *wl;
    unsigned char *qreh, *qrel, *qimh, *qiml, *kreh, *krel, *kimh, *kiml;
    unsigned char *vreh, *vrel, *vimh, *viml, *oreh, *orel, *oimh, *oiml;
    unsigned char *zreh, *zrel, *zimh, *ziml;
    cudaGetSymbolAddress((void**)&wh, g_wh);   cudaGetSymbolAddress((void**)&wl, g_wl);
    cudaGetSymbolAddress((void**)&qreh, g_qreh); cudaGetSymbolAddress((void**)&qrel, g_qrel);
    cudaGetSymbolAddress((void**)&qimh, g_qimh); cudaGetSymbolAddress((void**)&qiml, g_qiml);
    cudaGetSymbolAddress((void**)&kreh, g_kreh); cudaGetSymbolAddress((void**)&krel, g_krel);
    cudaGetSymbolAddress((void**)&kimh, g_kimh); cudaGetSymbolAddress((void**)&kiml, g_kiml);
    cudaGetSymbolAddress((void**)&vreh, g_vreh); cudaGetSymbolAddress((void**)&vrel, g_vrel);
    cudaGetSymbolAddress((void**)&vimh, g_vimh); cudaGetSymbolAddress((void**)&viml, g_viml);
    cudaGetSymbolAddress((void**)&oreh, g_oreh); cudaGetSymbolAddress((void**)&orel, g_orel);
    cudaGetSymbolAddress((void**)&oimh, g_oimh); cudaGetSymbolAddress((void**)&oiml, g_oiml);
    cudaGetSymbolAddress((void**)&zreh, g_zreh); cudaGetSymbolAddress((void**)&zrel, g_zrel);
    cudaGetSymbolAddress((void**)&zimh, g_zimh); cudaGetSymbolAddress((void**)&ziml, g_ziml);

    cudaFuncSetAttribute(gemm_qk,        cudaFuncAttributeMaxDynamicSharedMemorySize, QK_SM);
    cudaFuncSetAttribute(gemm_wB<true>,  cudaFuncAttributeMaxDynamicSharedMemorySize, WB_SM);
    cudaFuncSetAttribute(gemm_wB<false>, cudaFuncAttributeMaxDynamicSharedMemorySize, WB_SM);
    cudaFuncSetAttribute(gemm_scores,    cudaFuncAttributeMaxDynamicSharedMemorySize, SC_SM);
    cudaFuncSetAttribute(gemm_av,        cudaFuncAttributeMaxDynamicSharedMemorySize, WB_SM);

    float* out_re = (float*)d_out;
    float* out_im = out_re + (size_t)BCT;

    prep_z<<<dim3(32, 8, Bb), 256>>>(z_re, z_im);
    prep_w<<<dim3(8, 4), 256>>>(Wq, Wk, Wv, Wo);
    gemm_qk<<<dim3(8, 8, Bb), NT, QK_SM>>>(wh + 0*WBY, wl + 0*WBY, phi_q, qreh, qrel, qimh, qiml);
    gemm_qk<<<dim3(8, 8, Bb), NT, QK_SM>>>(wh + 1*WBY, wl + 1*WBY, phi_k, kreh, krel, kimh, kiml);
    gemm_wB<true><<<dim3(16, 4, Bb), NT, WB_SM>>>(wh + 2*WBY, wl + 2*WBY, phi_v,
        zreh, zrel, zimh, ziml, vreh, vrel, vimh, viml, nullptr, nullptr);
    gemm_scores<<<dim3(16, 8, Bb), NT, SC_SM>>>();
    softmax_kernel<<<dim3(Tt, Bb), 256>>>();
    gemm_av<<<dim3(8, 8, Bb), NT, WB_SM>>>();
    gemm_wB<false><<<dim3(16, 4, Bb), NT, WB_SM>>>(wh + 3*WBY, wl + 3*WBY, phi_o,
        oreh, orel, oimh, oiml, nullptr, nullptr, nullptr, nullptr, out_re, out_im);
}

// round 7
// speedup vs baseline: 2.5077x; 1.0121x over previous
#include <cuda_runtime.h>
#include <cuda_bf16.h>
#include <cstdint>
#include <math.h>

#define Bb 8
#define Cc 512
#define Tt 1024
#define BCT (Bb*Cc*Tt)
#define BTT (Bb*Tt*Tt)

// chunked bf16 tensor layout: [ch][R rows][128B], swizzled per-row:
// byte(col,row) = (col*2) ^ ((row&7)<<4)
#define ZB (8*1024*128)
#define VB (16*512*128)
#define AB (16*1024*128)
#define WBY (8*512*128)

__device__ __align__(16) unsigned char g_zreh[Bb*ZB], g_zrel[Bb*ZB], g_zimh[Bb*ZB], g_ziml[Bb*ZB];
__device__ __align__(16) unsigned char g_qreh[Bb*ZB], g_qrel[Bb*ZB], g_qimh[Bb*ZB], g_qiml[Bb*ZB];
__device__ __align__(16) unsigned char g_kreh[Bb*ZB], g_krel[Bb*ZB], g_kimh[Bb*ZB], g_kiml[Bb*ZB];
__device__ __align__(16) unsigned char g_vreh[Bb*VB], g_vrel[Bb*VB], g_vimh[Bb*VB], g_viml[Bb*VB];
__device__ __align__(16) unsigned char g_ath[Bb*AB],  g_atl[Bb*AB];
__device__ __align__(16) unsigned char g_oreh[Bb*ZB], g_orel[Bb*ZB], g_oimh[Bb*ZB], g_oiml[Bb*ZB];
__device__ __align__(16) unsigned char g_wh[4*WBY],   g_wl[4*WBY];
__device__ float g_attn[BTT];

#define SW128(o) ((o) ^ (((o) >> 3) & 0x70))
#define NT 512

__device__ __forceinline__ uint32_t s2u(const void* p) {
    uint32_t a;
    asm("{ .reg .u64 t; cvta.to.shared.u64 t, %1; cvt.u32.u64 %0, t; }" : "=r"(a) : "l"(p));
    return a;
}
__device__ __forceinline__ uint32_t pk2(__nv_bfloat16 a, __nv_bfloat16 b) {
    return ((uint32_t)__bfloat16_as_ushort(b) << 16) | (uint32_t)__bfloat16_as_ushort(a);
}
__device__ __forceinline__ void st_pair(unsigned char* bh, unsigned char* bl,
                                        int R, int ch, int row, int col, float v0, float v1) {
    size_t off = (((size_t)ch * R + row) << 7) + (uint32_t)((col * 2) ^ ((row & 7) << 4));
    __nv_bfloat16 h0 = __float2bfloat16(v0), h1 = __float2bfloat16(v1);
    *(uint32_t*)(bh + off) = pk2(h0, h1);
    __nv_bfloat16 l0 = __float2bfloat16(v0 - __bfloat162float(h0));
    __nv_bfloat16 l1 = __float2bfloat16(v1 - __bfloat162float(h1));
    *(uint32_t*)(bl + off) = pk2(l0, l1);
}
__device__ __forceinline__ void cpa16(uint32_t s, const void* g) {
    asm volatile("cp.async.cg.shared.global [%0], [%1], 16;" :: "r"(s), "l"(g) : "memory");
}
__device__ __forceinline__ void cpa_commit() { asm volatile("cp.async.commit_group;" ::: "memory"); }
__device__ __forceinline__ void cpa_wait1()  { asm volatile("cp.async.wait_group 1;" ::: "memory"); }
__device__ __forceinline__ void cpa_wait0()  { asm volatile("cp.async.wait_group 0;" ::: "memory"); }
__device__ __forceinline__ void cpreg(uint32_t s, const unsigned char* g, int nbytes, int tid) {
    for (int o = tid * 16; o < nbytes; o += NT * 16) cpa16(s + o, g + o);
}
__device__ __forceinline__ void ldsm4(uint32_t* r, uint32_t addr) {
    asm volatile("ldmatrix.sync.aligned.m8n8.x4.shared.b16 {%0,%1,%2,%3}, [%4];"
                 : "=r"(r[0]), "=r"(r[1]), "=r"(r[2]), "=r"(r[3]) : "r"(addr));
}
__device__ __forceinline__ void mma16816(float* d, const uint32_t* a, const uint32_t* b) {
    asm volatile(
        "mma.sync.aligned.m16n8k16.row.col.f32.bf16.bf16.f32 "
        "{%0,%1,%2,%3}, {%4,%5,%6,%7}, {%8,%9}, {%0,%1,%2,%3};"
        : "+f"(d[0]), "+f"(d[1]), "+f"(d[2]), "+f"(d[3])
        : "r"(a[0]), "r"(a[1]), "r"(a[2]), "r"(a[3]), "r"(b[0]), "r"(b[1]));
}
__device__ __forceinline__ void mma_split(float* d, const uint32_t* aH, const uint32_t* aL,
                                          const uint32_t* bH, const uint32_t* bL) {
    mma16816(d, aH, bH);
    mma16816(d, aH, bL);
    mma16816(d, aL, bH);
}
__device__ __forceinline__ uint32_t a_addr(uint32_t base, int mbase, int ks, int lane) {
    int row = mbase + (lane & 15);
    int byt = ks * 32 + ((lane >> 4) << 4);
    return base + SW128((uint32_t)(row * 128 + byt));
}
__device__ __forceinline__ uint32_t b_addr(uint32_t base, int nbase, int ks, int lane) {
    int row = nbase + ((lane >> 4) << 3) + (lane & 7);
    int byt = ks * 32 + (((lane >> 3) & 1) << 4);
    return base + SW128((uint32_t)(row * 128 + byt));
}

// ---------------------------------------------------------------------------
// prep_z: fp32 z[b][c][t] -> chunked bf16 hi/lo [b][c/64][t][128B] (transpose)
// ---------------------------------------------------------------------------
__global__ __launch_bounds__(256) void prep_z(
    const float* __restrict__ zre, const float* __restrict__ zim)
{
    __shared__ float sre[64][33], sim[64][33];
    const int b = blockIdx.z, t0 = blockIdx.x * 32, c0 = blockIdx.y * 64;
    const int tid = threadIdx.x;
    const float* pre = zre + (size_t)b * Cc * Tt;
    const float* pim = zim + (size_t)b * Cc * Tt;
    for (int i = tid; i < 2048; i += 256) {
        int cl = i >> 5, tl = i & 31;
        sre[cl][tl] = pre[(size_t)(c0 + cl) * Tt + t0 + tl];
        sim[cl][tl] = pim[(size_t)(c0 + cl) * Tt + t0 + tl];
    }
    __syncthreads();
    unsigned char* zrh = g_zreh + (size_t)b * ZB;
    unsigned char* zrl = g_zrel + (size_t)b * ZB;
    unsigned char* zih = g_zimh + (size_t)b * ZB;
    unsigned char* zil = g_ziml + (size_t)b * ZB;
    const int ch = c0 >> 6;
    for (int i = tid; i < 1024; i += 256) {
        int tl = i >> 5, p = i & 31;
        int t = t0 + tl, col = p * 2;
        st_pair(zrh, zrl, 1024, ch, t, col, sre[col][tl], sre[col + 1][tl]);
        st_pair(zih, zil, 1024, ch, t, col, sim[col][tl], sim[col + 1][tl]);
    }
}

// ---------------------------------------------------------------------------
__global__ __launch_bounds__(256) void prep_w(
    const float* __restrict__ W0, const float* __restrict__ W1,
    const float* __restrict__ W2, const float* __restrict__ W3)
{
    const int d0 = blockIdx.x * 64, wi = blockIdx.y, tid = threadIdx.x;
    const float* W = (wi == 0) ? W0 : (wi == 1) ? W1 : (wi == 2) ? W2 : W3;
    unsigned char* oh = g_wh + (size_t)wi * WBY;
    unsigned char* ol = g_wl + (size_t)wi * WBY;
    for (int i = tid; i < 8192; i += 256) {
        int dl = i >> 7, q = i & 127;
        int c = q * 4, d = d0 + dl;
        float4 v = *(const float4*)&W[(size_t)d * Cc + c];
        st_pair(oh, ol, 512, c >> 6, d, c & 63, v.x, v.y);
        st_pair(oh, ol, 512, c >> 6, d, (c & 63) + 2, v.z, v.w);
    }
}

// ---------------------------------------------------------------------------
// gemm_qk2: FUSED Q+K projection. D_q[t,d], D_k[t,d] from shared A = z tiles.
// 512 thr, warp grid 8m x 2n (warp tile 16 x 32 per W).
// grid (Cc/64=8, Tt/128=8, Bb). smem 2x98304 = 192KB.
// ---------------------------------------------------------------------------
#define QK2_STRIDE 98304
#define QK2_SM (2*QK2_STRIDE)
__global__ __launch_bounds__(NT) void gemm_qk2(
    const float* __restrict__ phi_q, const float* __restrict__ phi_k)
{
    extern __shared__ char sm[];
    __shared__ float csq[64], snq[64], csk[64], snk[64];
    const uint32_t smb = s2u(sm);
    const int tid = threadIdx.x, wid = tid >> 5, lane = tid & 31;
    const int wm = wid & 7, wn = wid >> 3;
    const int b = blockIdx.z, m0 = blockIdx.y * 128, n0 = blockIdx.x * 64;

    if (tid < 64) {
        float s, c;
        sincosf(phi_q[n0 + tid], &s, &c); csq[tid] = c; snq[tid] = s;
        sincosf(phi_k[n0 + tid], &s, &c); csk[tid] = c; snk[tid] = s;
    }

    const unsigned char* zrh = g_zreh + (size_t)b * ZB;
    const unsigned char* zrl = g_zrel + (size_t)b * ZB;
    const unsigned char* zih = g_zimh + (size_t)b * ZB;
    const unsigned char* zil = g_ziml + (size_t)b * ZB;
    const unsigned char* wqh = g_wh + 0 * (size_t)WBY;
    const unsigned char* wql = g_wl + 0 * (size_t)WBY;
    const unsigned char* wkh = g_wh + 1 * (size_t)WBY;
    const unsigned char* wkl = g_wl + 1 * (size_t)WBY;

    auto issue = [&](int ch, uint32_t bs) {
        size_t ao = ((size_t)(ch * 1024 + m0)) << 7;
        size_t bo = ((size_t)(ch * 512 + n0)) << 7;
        cpreg(bs + 0,     zrh + ao, 16384, tid);
        cpreg(bs + 16384, zrl + ao, 16384, tid);
        cpreg(bs + 32768, zih + ao, 16384, tid);
        cpreg(bs + 49152, zil + ao, 16384, tid);
        cpreg(bs + 65536, wqh + bo, 8192, tid);
        cpreg(bs + 73728, wql + bo, 8192, tid);
        cpreg(bs + 81920, wkh + bo, 8192, tid);
        cpreg(bs + 90112, wkl + bo, 8192, tid);
    };

    float accQR[4][4] = {}, accQI[4][4] = {}, accKR[4][4] = {}, accKI[4][4] = {};
    issue(0, smb); cpa_commit();
    for (int ch = 0; ch < 8; ch++) {
        uint32_t base = smb + (ch & 1) * QK2_STRIDE;
        if (ch + 1 < 8) { issue(ch + 1, smb + ((ch + 1) & 1) * QK2_STRIDE); cpa_commit(); cpa_wait1(); }
        else cpa_wait0();
        __syncthreads();
        #pragma unroll
        for (int ks = 0; ks < 4; ks++) {
            uint32_t arH[4], arL[4], aiH[4], aiL[4];
            ldsm4(arH, a_addr(base + 0,     wm * 16, ks, lane));
            ldsm4(arL, a_addr(base + 16384, wm * 16, ks, lane));
            ldsm4(aiH, a_addr(base + 32768, wm * 16, ks, lane));
            ldsm4(aiL, a_addr(base + 49152, wm * 16, ks, lane));
            uint32_t bH[8], bL[8];
            // Q weights
            ldsm4(bH + 0, b_addr(base + 65536, wn * 32,      ks, lane));
            ldsm4(bH + 4, b_addr(base + 65536, wn * 32 + 16, ks, lane));
            ldsm4(bL + 0, b_addr(base + 73728, wn * 32,      ks, lane));
            ldsm4(bL + 4, b_addr(base + 73728, wn * 32 + 16, ks, lane));
            #pragma unroll
            for (int nf = 0; nf < 4; nf++) {
                mma_split(accQR[nf], arH, arL, bH + nf * 2, bL + nf * 2);
                mma_split(accQI[nf], aiH, aiL, bH + nf * 2, bL + nf * 2);
            }
            // K weights (reuse B registers)
            ldsm4(bH + 0, b_addr(base + 81920, wn * 32,      ks, lane));
            ldsm4(bH + 4, b_addr(base + 81920, wn * 32 + 16, ks, lane));
            ldsm4(bL + 0, b_addr(base + 90112, wn * 32,      ks, lane));
            ldsm4(bL + 4, b_addr(base + 90112, wn * 32 + 16, ks, lane));
            #pragma unroll
            for (int nf = 0; nf < 4; nf++) {
                mma_split(accKR[nf], arH, arL, bH + nf * 2, bL + nf * 2);
                mma_split(accKI[nf], aiH, aiL, bH + nf * 2, bL + nf * 2);
            }
        }
        __syncthreads();
    }

    unsigned char* qrh = g_qreh + (size_t)b * ZB;
    unsigned char* qrl = g_qrel + (size_t)b * ZB;
    unsigned char* qih = g_qimh + (size_t)b * ZB;
    unsigned char* qil = g_qiml + (size_t)b * ZB;
    unsigned char* krh = g_kreh + (size_t)b * ZB;
    unsigned char* krl = g_krel + (size_t)b * ZB;
    unsigned char* kih = g_kimh + (size_t)b * ZB;
    unsigned char* kil = g_kiml + (size_t)b * ZB;
    const int g = lane >> 2, cp = (lane & 3) * 2, och = n0 >> 6;
    const int r0 = m0 + wm * 16 + g;
    #pragma unroll
    for (int nf = 0; nf < 4; nf++) {
        const int c = wn * 32 + nf * 8 + cp;
        float cq0 = csq[c], sq0 = snq[c], cq1 = csq[c + 1], sq1 = snq[c + 1];
        float ck0 = csk[c], sk0 = snk[c], ck1 = csk[c + 1], sk1 = snk[c + 1];
        float* qR = accQR[nf]; float* qI = accQI[nf];
        float* kR = accKR[nf]; float* kI = accKI[nf];
        st_pair(qrh, qrl, 1024, och, r0, c, qR[0]*cq0 - qI[0]*sq0, qR[1]*cq1 - qI[1]*sq1);
        st_pair(qih, qil, 1024, och, r0, c, qR[0]*sq0 + qI[0]*cq0, qR[1]*sq1 + qI[1]*cq1);
        st_pair(qrh, qrl, 1024, och, r0 + 8, c, qR[2]*cq0 - qI[2]*sq0, qR[3]*cq1 - qI[3]*sq1);
        st_pair(qih, qil, 1024, och, r0 + 8, c, qR[2]*sq0 + qI[2]*cq0, qR[3]*sq1 + qI[3]*cq1);
        st_pair(krh, krl, 1024, och, r0, c, kR[0]*ck0 - kI[0]*sk0, kR[1]*ck1 - kI[1]*sk1);
        st_pair(kih, kil, 1024, och, r0, c, kR[0]*sk0 + kI[0]*ck0, kR[1]*sk1 + kI[1]*ck1);
        st_pair(krh, krl, 1024, och, r0 + 8, c, kR[2]*ck0 - kI[2]*sk0, kR[3]*ck1 - kI[3]*sk1);
        st_pair(kih, kil, 1024, och, r0 + 8, c, kR[2]*sk0 + kI[2]*ck0, kR[3]*sk1 + kI[3]*ck1);
    }
}

// ---------------------------------------------------------------------------
// gemm_wB: D[d,n] = rot_row( W·Bᵀ ). grid (Tt/64=16, Cc/128=4, Bb). smem 2x65536.
// ---------------------------------------------------------------------------
#define WB_STRIDE 65536
#define WB_SM (2*WB_STRIDE)
template<bool BF16OUT>
__global__ __launch_bounds__(NT) void gemm_wB(
    const unsigned char* __restrict__ wh, const unsigned char* __restrict__ wl,
    const float* __restrict__ phi,
    const unsigned char* __restrict__ breh, const unsigned char* __restrict__ brel,
    const unsigned char* __restrict__ bimh, const unsigned char* __restrict__ biml,
    unsigned char* __restrict__ ovreh, unsigned char* __restrict__ ovrel,
    unsigned char* __restrict__ ovimh, unsigned char* __restrict__ oviml,
    float* __restrict__ fre, float* __restrict__ fim)
{
    extern __shared__ char sm[];
    __shared__ float s_cs[128], s_sn[128];
    const uint32_t smb = s2u(sm);
    const int tid = threadIdx.x, wid = tid >> 5, lane = tid & 31;
    const int wm = wid & 3, wn = wid >> 2;
    const int b = blockIdx.z, m0 = blockIdx.y * 128, n0 = blockIdx.x * 64;

    if (tid < 128) {
        float s, c; sincosf(phi[m0 + tid], &s, &c);
        s_cs[tid] = c; s_sn[tid] = s;
    }

    const unsigned char* brh = breh + (size_t)b * ZB;
    const unsigned char* brl = brel + (size_t)b * ZB;
    const unsigned char* bih = bimh + (size_t)b * ZB;
    const unsigned char* bil = biml + (size_t)b * ZB;

    auto issue = [&](int ch, uint32_t bs) {
        size_t ao = ((size_t)(ch * 512 + m0)) << 7;
        size_t bo = ((size_t)(ch * 1024 + n0)) << 7;
        cpreg(bs + 0,     wh + ao, 16384, tid);
        cpreg(bs + 16384, wl + ao, 16384, tid);
        cpreg(bs + 32768, brh + bo, 8192, tid);
        cpreg(bs + 40960, brl + bo, 8192, tid);
        cpreg(bs + 49152, bih + bo, 8192, tid);
        cpreg(bs + 57344, bil + bo, 8192, tid);
    };

    float accR[2][2][4] = {}, accI[2][2][4] = {};
    issue(0, smb); cpa_commit();
    for (int ch = 0; ch < 8; ch++) {
        uint32_t base = smb + (ch & 1) * WB_STRIDE;
        if (ch + 1 < 8) { issue(ch + 1, smb + ((ch + 1) & 1) * WB_STRIDE); cpa_commit(); cpa_wait1(); }
        else cpa_wait0();
        __syncthreads();
        #pragma unroll
        for (int ks = 0; ks < 4; ks++) {
            uint32_t aH[2][4], aL[2][4];
            #pragma unroll
            for (int mi = 0; mi < 2; mi++) {
                ldsm4(aH[mi], a_addr(base + 0,     wm * 32 + mi * 16, ks, lane));
                ldsm4(aL[mi], a_addr(base + 16384, wm * 32 + mi * 16, ks, lane));
            }
            uint32_t rH[4], rL[4], iH[4], iL[4];
            ldsm4(rH, b_addr(base + 32768, wn * 16, ks, lane));
            ldsm4(rL, b_addr(base + 40960, wn * 16, ks, lane));
            ldsm4(iH, b_addr(base + 49152, wn * 16, ks, lane));
            ldsm4(iL, b_addr(base + 57344, wn * 16, ks, lane));
            #pragma unroll
            for (int mi = 0; mi < 2; mi++)
                #pragma unroll
                for (int nf = 0; nf < 2; nf++) {
                    mma_split(accR[mi][nf], aH[mi], aL[mi], rH + nf * 2, rL + nf * 2);
                    mma_split(accI[mi][nf], aH[mi], aL[mi], iH + nf * 2, iL + nf * 2);
                }
        }
        __syncthreads();
    }

    const int g = lane >> 2, cp = (lane & 3) * 2;
    #pragma unroll
    for (int mi = 0; mi < 2; mi++) {
        const int lr = wm * 32 + mi * 16 + g;
        const float c0 = s_cs[lr], s0 = s_sn[lr], c8 = s_cs[lr + 8], s8 = s_sn[lr + 8];
        const int r0 = m0 + lr;
        #pragma unroll
        for (int nf = 0; nf < 2; nf++) {
            const int c = wn * 16 + nf * 8 + cp;
            float* aR = accR[mi][nf];
            float* aI = accI[mi][nf];
            float xr0 = aR[0]*c0 - aI[0]*s0, xr1 = aR[1]*c0 - aI[1]*s0;
            float xi0 = aR[0]*s0 + aI[0]*c0, xi1 = aR[1]*s0 + aI[1]*c0;
            float yr0 = aR[2]*c8 - aI[2]*s8, yr1 = aR[3]*c8 - aI[3]*s8;
            float yi0 = aR[2]*s8 + aI[2]*c8, yi1 = aR[3]*s8 + aI[3]*c8;
            if (BF16OUT) {
                unsigned char* vrh = ovreh + (size_t)b * VB;
                unsigned char* vrl = ovrel + (size_t)b * VB;
                unsigned char* vih = ovimh + (size_t)b * VB;
                unsigned char* vil = oviml + (size_t)b * VB;
                st_pair(vrh, vrl, 512, n0 >> 6, r0, c, xr0, xr1);
                st_pair(vih, vil, 512, n0 >> 6, r0, c, xi0, xi1);
                st_pair(vrh, vrl, 512, n0 >> 6, r0 + 8, c, yr0, yr1);
                st_pair(vih, vil, 512, n0 >> 6, r0 + 8, c, yi0, yi1);
            } else {
                float* dre = fre + (size_t)b * Cc * Tt;
                float* dim = fim + (size_t)b * Cc * Tt;
                *(float2*)&dre[(size_t)r0 * Tt + n0 + c]       = make_float2(xr0, xr1);
                *(float2*)&dim[(size_t)r0 * Tt + n0 + c]       = make_float2(xi0, xi1);
                *(float2*)&dre[(size_t)(r0 + 8) * Tt + n0 + c] = make_float2(yr0, yr1);
                *(float2*)&dim[(size_t)(r0 + 8) * Tt + n0 + c] = make_float2(yi0, yi1);
            }
        }
    }
}

// ---------------------------------------------------------------------------
// gemm_scores: S[t,u] = (Q·Kᵀre + im)/8. Masking deferred to softmax; fully
// masked tiles skipped entirely. grid (16, 8, Bb). smem 2x98304.
// ---------------------------------------------------------------------------
#define SC_STRIDE 98304
#define SC_SM (2*SC_STRIDE)
__global__ __launch_bounds__(NT) void gemm_scores()
{
    extern __shared__ char sm[];
    const uint32_t smb = s2u(sm);
    const int tid = threadIdx.x, wid = tid >> 5, lane = tid & 31;
    const int wm = wid & 3, wn = wid >> 2;
    const int b = blockIdx.z, m0 = blockIdx.y * 128, n0 = blockIdx.x * 64;
    if (n0 >= m0 + 128) return;   // fully masked — softmax masks reads
    float* arow = g_attn + (size_t)b * Tt * Tt;

    const unsigned char* qrh = g_qreh + (size_t)b * ZB;
    const unsigned char* qrl = g_qrel + (size_t)b * ZB;
    const unsigned char* qih = g_qimh + (size_t)b * ZB;
    const unsigned char* qil = g_qiml + (size_t)b * ZB;
    const unsigned char* krh = g_kreh + (size_t)b * ZB;
    const unsigned char* krl = g_krel + (size_t)b * ZB;
    const unsigned char* kih = g_kimh + (size_t)b * ZB;
    const unsigned char* kil = g_kiml + (size_t)b * ZB;

    auto issue = [&](int ch, uint32_t bs) {
        size_t ao = ((size_t)(ch * 1024 + m0)) << 7;
        size_t bo = ((size_t)(ch * 1024 + n0)) << 7;
        cpreg(bs + 0,     qrh + ao, 16384, tid);
        cpreg(bs + 16384, qrl + ao, 16384, tid);
        cpreg(bs + 32768, qih + ao, 16384, tid);
        cpreg(bs + 49152, qil + ao, 16384, tid);
        cpreg(bs + 65536, krh + bo, 8192, tid);
        cpreg(bs + 73728, krl + bo, 8192, tid);
        cpreg(bs + 81920, kih + bo, 8192, tid);
        cpreg(bs + 90112, kil + bo, 8192, tid);
    };

    float acc[2][2][4] = {};
    issue(0, smb); cpa_commit();
    for (int ch = 0; ch < 8; ch++) {
        uint32_t base = smb + (ch & 1) * SC_STRIDE;
        if (ch + 1 < 8) { issue(ch + 1, smb + ((ch + 1) & 1) * SC_STRIDE); cpa_commit(); cpa_wait1(); }
        else cpa_wait0();
        __syncthreads();
        #pragma unroll
        for (int ks = 0; ks < 4; ks++) {
            uint32_t qRH[2][4], qRL[2][4], qIH[2][4], qIL[2][4];
            #pragma unroll
            for (int mi = 0; mi < 2; mi++) {
                ldsm4(qRH[mi], a_addr(base + 0,     wm * 32 + mi * 16, ks, lane));
                ldsm4(qRL[mi], a_addr(base + 16384, wm * 32 + mi * 16, ks, lane));
                ldsm4(qIH[mi], a_addr(base + 32768, wm * 32 + mi * 16, ks, lane));
                ldsm4(qIL[mi], a_addr(base + 49152, wm * 32 + mi * 16, ks, lane));
            }
            uint32_t rH[4], rL[4], iH[4], iL[4];
            ldsm4(rH, b_addr(base + 65536, wn * 16, ks, lane));
            ldsm4(rL, b_addr(base + 73728, wn * 16, ks, lane));
            ldsm4(iH, b_addr(base + 81920, wn * 16, ks, lane));
            ldsm4(iL, b_addr(base + 90112, wn * 16, ks, lane));
            #pragma unroll
            for (int mi = 0; mi < 2; mi++)
                #pragma unroll
                for (int nf = 0; nf < 2; nf++) {
                    mma_split(acc[mi][nf], qRH[mi], qRL[mi], rH + nf * 2, rL + nf * 2);
                    mma_split(acc[mi][nf], qIH[mi], qIL[mi], iH + nf * 2, iL + nf * 2);
                }
        }
        __syncthreads();
    }

    const int g = lane >> 2, cp = (lane & 3) * 2;
    #pragma unroll
    for (int mi = 0; mi < 2; mi++) {
        const int r0 = m0 + wm * 32 + mi * 16 + g;
        #pragma unroll
        for (int nf = 0; nf < 2; nf++) {
            const int u = n0 + wn * 16 + nf * 8 + cp;
            float* a = acc[mi][nf];
            *(float2*)&arow[(size_t)r0 * Tt + u]       = make_float2(a[0] * 0.125f, a[1] * 0.125f);
            *(float2*)&arow[(size_t)(r0 + 8) * Tt + u] = make_float2(a[2] * 0.125f, a[3] * 0.125f);
        }
    }
}

// ---------------------------------------------------------------------------
// softmax: applies causal mask (u > t -> -inf), fp32 -> bf16 hi/lo chunked attn.
// ---------------------------------------------------------------------------
__global__ __launch_bounds__(256) void softmax_kernel()
{
    const int t = blockIdx.x, b = blockIdx.y;
    const float* row = g_attn + ((size_t)b * Tt + t) * Tt;
    const int tid = threadIdx.x;
    const float ni = __int_as_float(0xff800000);
    const int u0 = tid * 4;
    float4 v = ((const float4*)row)[tid];
    if (u0     > t) v.x = ni;
    if (u0 + 1 > t) v.y = ni;
    if (u0 + 2 > t) v.z = ni;
    if (u0 + 3 > t) v.w = ni;
    float m = fmaxf(fmaxf(v.x, v.y), fmaxf(v.z, v.w));
    __shared__ float red[8];
    #pragma unroll
    for (int o = 16; o > 0; o >>= 1) m = fmaxf(m, __shfl_xor_sync(0xffffffffu, m, o));
    if ((tid & 31) == 0) red[tid >> 5] = m;
    __syncthreads();
    if (tid == 0) {
        float mm = red[0];
        #pragma unroll
        for (int i = 1; i < 8; i++) mm = fmaxf(mm, red[i]);
        red[0] = mm;
    }
    __syncthreads();
    m = red[0];
    __syncthreads();
    float e0 = expf(v.x - m), e1 = expf(v.y - m), e2 = expf(v.z - m), e3 = expf(v.w - m);
    float s = e0 + e1 + e2 + e3;
    #pragma unroll
    for (int o = 16; o > 0; o >>= 1) s += __shfl_xor_sync(0xffffffffu, s, o);
    if ((tid & 31) == 0) red[tid >> 5] = s;
    __syncthreads();
    if (tid == 0) {
        float ss = 0.f;
        #pragma unroll
        for (int i = 0; i < 8; i++) ss += red[i];
        red[0] = ss;
    }
    __syncthreads();
    const float inv = 1.0f / red[0];
    unsigned char* ah = g_ath + (size_t)b * AB;
    unsigned char* al = g_atl + (size_t)b * AB;
    st_pair(ah, al, 1024, u0 >> 6, t, u0 & 63, e0 * inv, e1 * inv);
    st_pair(ah, al, 1024, u0 >> 6, t, (u0 & 63) + 2, e2 * inv, e3 * inv);
}

// ---------------------------------------------------------------------------
// gemm_av: O[t,c] = attn·Vᵀ. K bounded causally. grid (8, 8, Bb). smem 2x65536.
// ---------------------------------------------------------------------------
__global__ __launch_bounds__(NT) void gemm_av()
{
    extern __shared__ char sm[];
    const uint32_t smb = s2u(sm);
    const int tid = threadIdx.x, wid = tid >> 5, lane = tid & 31;
    const int wm = wid & 3, wn = wid >> 2;
    const int b = blockIdx.z, m0 = blockIdx.y * 128, n0 = blockIdx.x * 64;

    const unsigned char* ah = g_ath + (size_t)b * AB;
    const unsigned char* al = g_atl + (size_t)b * AB;
    const unsigned char* vrh = g_vreh + (size_t)b * VB;
    const unsigned char* vrl = g_vrel + (size_t)b * VB;
    const unsigned char* vih = g_vimh + (size_t)b * VB;
    const unsigned char* vil = g_viml + (size_t)b * VB;

    auto issue = [&](int ch, uint32_t bs) {
        size_t ao = ((size_t)(ch * 1024 + m0)) << 7;
        size_t bo = ((size_t)(ch * 512 + n0)) << 7;
        cpreg(bs + 0,     ah + ao, 16384, tid);
        cpreg(bs + 16384, al + ao, 16384, tid);
        cpreg(bs + 32768, vrh + bo, 8192, tid);
        cpreg(bs + 40960, vrl + bo, 8192, tid);
        cpreg(bs + 49152, vih + bo, 8192, tid);
        cpreg(bs + 57344, vil + bo, 8192, tid);
    };

    float accR[2][2][4] = {}, accI[2][2][4] = {};
    const int nch = m0 / 64 + 2;
    issue(0, smb); cpa_commit();
    for (int ch = 0; ch < nch; ch++) {
        uint32_t base = smb + (ch & 1) * WB_STRIDE;
        if (ch + 1 < nch) { issue(ch + 1, smb + ((ch + 1) & 1) * WB_STRIDE); cpa_commit(); cpa_wait1(); }
        else cpa_wait0();
        __syncthreads();
        #pragma unroll
        for (int ks = 0; ks < 4; ks++) {
            uint32_t aH[2][4], aL[2][4];
            #pragma unroll
            for (int mi = 0; mi < 2; mi++) {
                ldsm4(aH[mi], a_addr(base + 0,     wm * 32 + mi * 16, ks, lane));
                ldsm4(aL[mi], a_addr(base + 16384, wm * 32 + mi * 16, ks, lane));
            }
            uint32_t rH[4], rL[4], iH[4], iL[4];
            ldsm4(rH, b_addr(base + 32768, wn * 16, ks, lane));
            ldsm4(rL, b_addr(base + 40960, wn * 16, ks, lane));
            ldsm4(iH, b_addr(base + 49152, wn * 16, ks, lane));
            ldsm4(iL, b_addr(base + 57344, wn * 16, ks, lane));
            #pragma unroll
            for (int mi = 0; mi < 2; mi++)
                #pragma unroll
                for (int nf = 0; nf < 2; nf++) {
                    mma_split(accR[mi][nf], aH[mi], aL[mi], rH + nf * 2, rL + nf * 2);
                    mma_split(accI[mi][nf], aH[mi], aL[mi], iH + nf * 2, iL + nf * 2);
                }
        }
        __syncthreads();
    }

    unsigned char* orh = g_oreh + (size_t)b * ZB;
    unsigned char* orl = g_orel + (size_t)b * ZB;
    unsigned char* oih = g_oimh + (size_t)b * ZB;
    unsigned char* oil = g_oiml + (size_t)b * ZB;
    const int g = lane >> 2, cp = (lane & 3) * 2, och = n0 >> 6;
    #pragma unroll
    for (int mi = 0; mi < 2; mi++) {
        const int r0 = m0 + wm * 32 + mi * 16 + g;
        #pragma unroll
        for (int nf = 0; nf < 2; nf++) {
            const int c = wn * 16 + nf * 8 + cp;
            float* aR = accR[mi][nf];
            float* aI = accI[mi][nf];
            st_pair(orh, orl, 1024, och, r0, c, aR[0], aR[1]);
            st_pair(oih, oil, 1024, och, r0, c, aI[0], aI[1]);
            st_pair(orh, orl, 1024, och, r0 + 8, c, aR[2], aR[3]);
            st_pair(oih, oil, 1024, och, r0 + 8, c, aI[2], aI[3]);
        }
    }
}

// ---------------------------------------------------------------------------
extern "C" void kernel_launch(void* const* d_in, const int* in_sizes, int n_in,
                              void* d_out, int out_size)
{
    const float* z_re  = (const float*)d_in[0];
    const float* z_im  = (const float*)d_in[1];
    const float* Wq    = (const float*)d_in[2];
    const float* phi_q = (const float*)d_in[3];
    const float* Wk    = (const float*)d_in[4];
    const float* phi_k = (const float*)d_in[5];
    const float* Wv    = (const float*)d_in[6];
    const float* phi_v = (const float*)d_in[7];
    const float* Wo    = (const float*)d_in[8];
    const float* phi_o = (const float*)d_in[9];

    unsigned char *wh, *wl;
    unsigned char *vreh, *vrel, *vimh, *viml, *oreh, *orel, *oimh, *oiml;
    unsigned char *zreh, *zrel, *zimh, *ziml;
    cudaGetSymbolAddress((void**)&wh, g_wh);   cudaGetSymbolAddress((void**)&wl, g_wl);
    cudaGetSymbolAddress((void**)&vreh, g_vreh); cudaGetSymbolAddress((void**)&vrel, g_vrel);
    cudaGetSymbolAddress((void**)&vimh, g_vimh); cudaGetSymbolAddress((void**)&viml, g_viml);
    cudaGetSymbolAddress((void**)&oreh, g_oreh); cudaGetSymbolAddress((void**)&orel, g_orel);
    cudaGetSymbolAddress((void**)&oimh, g_oimh); cudaGetSymbolAddress((void**)&oiml, g_oiml);
    cudaGetSymbolAddress((void**)&zreh, g_zreh); cudaGetSymbolAddress((void**)&zrel, g_zrel);
    cudaGetSymbolAddress((void**)&zimh, g_zimh); cudaGetSymbolAddress((void**)&ziml, g_ziml);

    cudaFuncSetAttribute(gemm_qk2,       cudaFuncAttributeMaxDynamicSharedMemorySize, QK2_SM);
    cudaFuncSetAttribute(gemm_wB<true>,  cudaFuncAttributeMaxDynamicSharedMemorySize, WB_SM);
    cudaFuncSetAttribute(gemm_wB<false>, cudaFuncAttributeMaxDynamicSharedMemorySize, WB_SM);
    cudaFuncSetAttribute(gemm_scores,    cudaFuncAttributeMaxDynamicSharedMemorySize, SC_SM);
    cudaFuncSetAttribute(gemm_av,        cudaFuncAttributeMaxDynamicSharedMemorySize, WB_SM);

    float* out_re = (float*)d_out;
    float* out_im = out_re + (size_t)BCT;

    prep_z<<<dim3(32, 8, Bb), 256>>>(z_re, z_im);
    prep_w<<<dim3(8, 4), 256>>>(Wq, Wk, Wv, Wo);
    gemm_qk2<<<dim3(8, 8, Bb), NT, QK2_SM>>>(phi_q, phi_k);
    gemm_wB<true><<<dim3(16, 4, Bb), NT, WB_SM>>>(wh + 2*WBY, wl + 2*WBY, phi_v,
        zreh, zrel, zimh, ziml, vreh, vrel, vimh, viml, nullptr, nullptr);
    gemm_scores<<<dim3(16, 8, Bb), NT, SC_SM>>>();
    softmax_kernel<<<dim3(Tt, Bb), 256>>>();
    gemm_av<<<dim3(8, 8, Bb), NT, WB_SM>>>();
    gemm_wB<false><<<dim3(16, 4, Bb), NT, WB_SM>>>(wh + 3*WBY, wl + 3*WBY, phi_o,
        oreh, orel, oimh, oiml, nullptr, nullptr, nullptr, nullptr, out_re, out_im);
}